// round 1
// baseline (speedup 1.0000x reference)
#include <cuda_runtime.h>
#include <math.h>
#include <stddef.h>

#define B_  32
#define N_  8192
#define DI  128
#define D_  512
#define NC  1000
#define TT  32            // items per tile
#define NT  (N_ / TT)     // 256 tiles per batch

// ---------------- device scratch (static allocation only) ----------------
__device__ float g_qk[B_ * D_];          // W_k^T q per batch
__device__ float g_qkb[B_];              // q . k_b per batch
__device__ float g_pm[B_ * NT];          // per-tile softmax max
__device__ float g_pl[B_ * NT];          // per-tile softmax sum
__device__ float g_pacc[B_ * NT * D_];   // per-tile weighted h2 accum (16.8 MB)

__device__ __forceinline__ float gelu_f(float x) {
    // exact GELU: 0.5 x (1 + erf(x / sqrt(2)))
    return 0.5f * x * (1.0f + erff(x * 0.70710678118654752440f));
}

// =========================================================================
// Kernel 1: query path. h_q MLP -> q -> fold through k_w.
// grid = B_, block = 512
// =========================================================================
__global__ __launch_bounds__(512) void k_query(
    const float* __restrict__ x_query,
    const float* __restrict__ w1, const float* __restrict__ b1,   // psi_q_w1 [512,1], b1 [512]
    const float* __restrict__ w2, const float* __restrict__ b2,   // psi_q_w2 [512,512]
    const float* __restrict__ qw, const float* __restrict__ qb,   // q_w [512,512]
    const float* __restrict__ kw, const float* __restrict__ kb)   // k_w [512,512]
{
    __shared__ float h1[D_], h2[D_], qv[D_];
    __shared__ float red[16];
    const int b = blockIdx.x;
    const int j = threadIdx.x;

    const float xq = x_query[b];
    h1[j] = gelu_f(fmaf(xq, w1[j], b1[j]));
    __syncthreads();

    {
        const float4* wr = (const float4*)(w2 + (size_t)j * D_);
        float s = 0.f;
        #pragma unroll 8
        for (int i = 0; i < D_ / 4; i++) {
            float4 w = wr[i];
            s += w.x * h1[4*i] + w.y * h1[4*i+1] + w.z * h1[4*i+2] + w.w * h1[4*i+3];
        }
        h2[j] = s + b2[j];
    }
    __syncthreads();
    {
        const float4* wr = (const float4*)(qw + (size_t)j * D_);
        float s = 0.f;
        #pragma unroll 8
        for (int i = 0; i < D_ / 4; i++) {
            float4 w = wr[i];
            s += w.x * h2[4*i] + w.y * h2[4*i+1] + w.z * h2[4*i+2] + w.w * h2[4*i+3];
        }
        qv[j] = s + qb[j];
    }
    __syncthreads();

    // qk[b][j] = sum_jj qv[jj] * kw[jj*512 + j]   (coalesced over j)
    {
        float s = 0.f;
        #pragma unroll 8
        for (int jj = 0; jj < D_; jj++) s = fmaf(qv[jj], kw[(size_t)jj * D_ + j], s);
        g_qk[b * D_ + j] = s;
    }
    // qkb = q . k_b
    {
        float p = qv[j] * kb[j];
        for (int o = 16; o; o >>= 1) p += __shfl_down_sync(0xffffffffu, p, o);
        if ((j & 31) == 0) red[j >> 5] = p;
        __syncthreads();
        if (j == 0) {
            float t = 0.f;
            for (int i = 0; i < 16; i++) t += red[i];
            g_qkb[b] = t;
        }
    }
}

// =========================================================================
// Kernel 2: fused item MLP + score + per-tile softmax partials.
// grid = (NT, B_), block = 256, dynamic smem.
// =========================================================================
#define XT_STRIDE 36    // k-major A tile stride (32 items padded)
#define W_STRIDE  132   // staged weight tile stride (128 cols padded)
#define H2_STRIDE 520   // row-major H2 stride (512 padded)

#define OFF_XT 0                       // 128*36  = 4608
#define OFF_H1 4608                    // 512*36  = 18432
#define OFF_W  (4608 + 18432)          // 23040; 32*132 = 4224
#define OFF_H2 (23040 + 4224)          // 27264; 32*520 = 16640
#define OFF_S  (27264 + 16640)         // 43904; 32 scores
#define OFF_P  (43904 + 32)            // 43936; 32 probs
#define SMEM_FLOATS 43972
#define SMEM_BYTES (SMEM_FLOATS * 4)

// C[32 x 512] = act(A[KD x 32 k-major] . W[512 x KD]^T + bias)
// thread layout: tx = tid&31 (4 cols each), ty = tid>>5 (4 rows each)
__device__ __forceinline__ void gemm_tile(
    const float* __restrict__ sA, int KD,
    const float* __restrict__ W, const float* __restrict__ bias,
    bool act, float* sW, float* out, bool out_kmajor,
    int tid, int tx, int ty)
{
    for (int j0 = 0; j0 < D_; j0 += 128) {
        float acc[4][4] = {};
        for (int k0 = 0; k0 < KD; k0 += 32) {
            __syncthreads();
            // stage sW[kk][jj] = W[(j0+jj)*KD + k0 + kk], jj<128, kk<32
            #pragma unroll
            for (int it = 0; it < 4; it++) {
                int e  = it * 256 + tid;   // 0..1023
                int jj = e >> 3;
                int kq = e & 7;
                float4 v = *(const float4*)(W + (size_t)(j0 + jj) * KD + k0 + kq * 4);
                int kk = kq * 4;
                sW[(kk + 0) * W_STRIDE + jj] = v.x;
                sW[(kk + 1) * W_STRIDE + jj] = v.y;
                sW[(kk + 2) * W_STRIDE + jj] = v.z;
                sW[(kk + 3) * W_STRIDE + jj] = v.w;
            }
            __syncthreads();
            const float* Ap = sA + (size_t)k0 * XT_STRIDE + ty * 4;
            const float* Wp = sW + tx * 4;
            #pragma unroll
            for (int kk = 0; kk < 32; kk++) {
                float4 a = *(const float4*)(Ap + kk * XT_STRIDE);
                float4 w = *(const float4*)(Wp + kk * W_STRIDE);
                acc[0][0] = fmaf(a.x, w.x, acc[0][0]);
                acc[0][1] = fmaf(a.x, w.y, acc[0][1]);
                acc[0][2] = fmaf(a.x, w.z, acc[0][2]);
                acc[0][3] = fmaf(a.x, w.w, acc[0][3]);
                acc[1][0] = fmaf(a.y, w.x, acc[1][0]);
                acc[1][1] = fmaf(a.y, w.y, acc[1][1]);
                acc[1][2] = fmaf(a.y, w.z, acc[1][2]);
                acc[1][3] = fmaf(a.y, w.w, acc[1][3]);
                acc[2][0] = fmaf(a.z, w.x, acc[2][0]);
                acc[2][1] = fmaf(a.z, w.y, acc[2][1]);
                acc[2][2] = fmaf(a.z, w.z, acc[2][2]);
                acc[2][3] = fmaf(a.z, w.w, acc[2][3]);
                acc[3][0] = fmaf(a.w, w.x, acc[3][0]);
                acc[3][1] = fmaf(a.w, w.y, acc[3][1]);
                acc[3][2] = fmaf(a.w, w.z, acc[3][2]);
                acc[3][3] = fmaf(a.w, w.w, acc[3][3]);
            }
        }
        float bv[4];
        #pragma unroll
        for (int c = 0; c < 4; c++) bv[c] = bias[j0 + tx * 4 + c];
        #pragma unroll
        for (int r = 0; r < 4; r++)
            #pragma unroll
            for (int c = 0; c < 4; c++) {
                float v = acc[r][c] + bv[c];
                acc[r][c] = act ? gelu_f(v) : v;
            }
        if (out_kmajor) {
            #pragma unroll
            for (int c = 0; c < 4; c++) {
                int jj = j0 + tx * 4 + c;
                float4 v = make_float4(acc[0][c], acc[1][c], acc[2][c], acc[3][c]);
                *(float4*)(out + (size_t)jj * XT_STRIDE + ty * 4) = v;
            }
        } else {
            #pragma unroll
            for (int r = 0; r < 4; r++) {
                int t = ty * 4 + r;
                float4 v = make_float4(acc[r][0], acc[r][1], acc[r][2], acc[r][3]);
                *(float4*)(out + (size_t)t * H2_STRIDE + j0 + tx * 4) = v;
            }
        }
    }
}

__global__ __launch_bounds__(256, 1) void k_main(
    const float* __restrict__ x_items,
    const float* __restrict__ w1, const float* __restrict__ b1,   // psi_x_w1 [512,128]
    const float* __restrict__ w2, const float* __restrict__ b2)   // psi_x_w2 [512,512]
{
    extern __shared__ float sm[];
    float* sXt = sm + OFF_XT;
    float* sH1 = sm + OFF_H1;
    float* sW  = sm + OFF_W;
    float* sH2 = sm + OFF_H2;
    float* sS  = sm + OFF_S;
    float* sP  = sm + OFF_P;

    const int tile = blockIdx.x;
    const int b    = blockIdx.y;
    const int tid  = threadIdx.x;
    const int tx   = tid & 31;
    const int ty   = tid >> 5;
    const int n0   = tile * TT;

    // load X tile transposed: sXt[i][t]
    {
        const float4* src = (const float4*)(x_items + ((size_t)b * N_ + n0) * DI);
        #pragma unroll
        for (int it = 0; it < 4; it++) {
            int e  = it * 256 + tid;         // 0..1023 of 32*32 float4s
            int t  = e >> 5;
            int iq = e & 31;
            float4 v = src[t * (DI / 4) + iq];
            int i0 = iq * 4;
            sXt[(i0 + 0) * XT_STRIDE + t] = v.x;
            sXt[(i0 + 1) * XT_STRIDE + t] = v.y;
            sXt[(i0 + 2) * XT_STRIDE + t] = v.z;
            sXt[(i0 + 3) * XT_STRIDE + t] = v.w;
        }
    }
    // (gemm_tile syncs before first staging, covering sXt writes)

    // H1 = gelu(X @ W1^T + b1)   -> k-major
    gemm_tile(sXt, DI, w1, b1, true, sW, sH1, true, tid, tx, ty);
    // H2 = H1 @ W2^T + b2        -> row-major
    gemm_tile(sH1, D_, w2, b2, false, sW, sH2, false, tid, tx, ty);
    __syncthreads();

    // scores: s[t] = (H2[t] . qk[b] + qkb[b]) / sqrt(512)
    {
        int t  = tid >> 3;
        int l8 = tid & 7;
        const float* qkp = g_qk + b * D_;
        const float* row = sH2 + (size_t)t * H2_STRIDE;
        float s = 0.f;
        int j0 = l8 * 64;
        #pragma unroll
        for (int j = 0; j < 64; j += 4) {
            float4 hv = *(const float4*)(row + j0 + j);
            float4 qv = *(const float4*)(qkp + j0 + j);
            s += hv.x * qv.x + hv.y * qv.y + hv.z * qv.z + hv.w * qv.w;
        }
        s += __shfl_down_sync(0xffffffffu, s, 4);
        s += __shfl_down_sync(0xffffffffu, s, 2);
        s += __shfl_down_sync(0xffffffffu, s, 1);
        if (l8 == 0) sS[t] = (s + g_qkb[b]) * 0.044194173824159216f;  // 512^-0.5
    }
    __syncthreads();

    // per-tile softmax partials (warp 0)
    if (tid < 32) {
        float sv = sS[tid];
        float m = sv;
        for (int o = 16; o; o >>= 1) m = fmaxf(m, __shfl_xor_sync(0xffffffffu, m, o));
        float p = __expf(sv - m) ;
        // use exact expf for safety
        p = expf(sv - m);
        float l = p;
        for (int o = 16; o; o >>= 1) l += __shfl_xor_sync(0xffffffffu, l, o);
        sP[tid] = p;
        if (tid == 0) {
            g_pm[b * NT + tile] = m;
            g_pl[b * NT + tile] = l;
        }
    }
    __syncthreads();

    // weighted accumulate: acc[j] = sum_t p[t] * H2[t][j]
    {
        float* dst = g_pacc + ((size_t)(b * NT + tile)) * D_;
        #pragma unroll
        for (int j = tid; j < D_; j += 256) {
            float a = 0.f;
            #pragma unroll
            for (int t = 0; t < TT; t++) a = fmaf(sP[t], sH2[(size_t)t * H2_STRIDE + j], a);
            dst[j] = a;
        }
    }
}

// =========================================================================
// Kernel 3: combine tile partials, folded V projection, phi MLP, output.
// grid = B_, block = NT (256)
// =========================================================================
__global__ __launch_bounds__(256) void k_final(
    const float* __restrict__ vw, const float* __restrict__ vb,
    const float* __restrict__ pw1, const float* __restrict__ pb1,
    const float* __restrict__ pw2, const float* __restrict__ pb2,
    float* __restrict__ out)
{
    __shared__ float s_scale[NT];
    __shared__ float s_zh[D_];
    __shared__ float s_z[D_];
    __shared__ float s_h[D_];
    __shared__ float s_red[8];
    __shared__ float s_M, s_L;

    const int b   = blockIdx.x;
    const int tid = threadIdx.x;
    const int lane = tid & 31, warp = tid >> 5;

    const float m = g_pm[b * NT + tid];
    // block max
    float mw = m;
    for (int o = 16; o; o >>= 1) mw = fmaxf(mw, __shfl_xor_sync(0xffffffffu, mw, o));
    if (lane == 0) s_red[warp] = mw;
    __syncthreads();
    if (tid == 0) {
        float t = s_red[0];
        for (int i = 1; i < 8; i++) t = fmaxf(t, s_red[i]);
        s_M = t;
    }
    __syncthreads();
    const float M = s_M;
    const float sc = expf(m - M);
    s_scale[tid] = sc;
    // block sum of l_i * scale_i
    float lp = g_pl[b * NT + tid] * sc;
    for (int o = 16; o; o >>= 1) lp += __shfl_xor_sync(0xffffffffu, lp, o);
    __syncthreads();
    if (lane == 0) s_red[warp] = lp;
    __syncthreads();
    if (tid == 0) {
        float t = 0.f;
        for (int i = 0; i < 8; i++) t += s_red[i];
        s_L = t;
    }
    __syncthreads();
    const float invL = 1.0f / s_L;

    // zh[j] = sum_i acc[i][j] * scale_i / L
    for (int j = tid; j < D_; j += 256) {
        const float* base = g_pacc + ((size_t)b * NT) * D_ + j;
        float s = 0.f;
        #pragma unroll 8
        for (int i = 0; i < NT; i++) s = fmaf(base[(size_t)i * D_], s_scale[i], s);
        s_zh[j] = s * invL;
    }
    __syncthreads();

    // z = zh @ vw^T + vb
    for (int j = tid; j < D_; j += 256) {
        const float4* wr = (const float4*)(vw + (size_t)j * D_);
        float s = 0.f;
        #pragma unroll 8
        for (int i = 0; i < D_ / 4; i++) {
            float4 w = wr[i];
            s += w.x * s_zh[4*i] + w.y * s_zh[4*i+1] + w.z * s_zh[4*i+2] + w.w * s_zh[4*i+3];
        }
        s_z[j] = s + vb[j];
    }
    __syncthreads();

    // h = gelu(z @ pw1^T + pb1)
    for (int j = tid; j < D_; j += 256) {
        const float4* wr = (const float4*)(pw1 + (size_t)j * D_);
        float s = 0.f;
        #pragma unroll 8
        for (int i = 0; i < D_ / 4; i++) {
            float4 w = wr[i];
            s += w.x * s_z[4*i] + w.y * s_z[4*i+1] + w.z * s_z[4*i+2] + w.w * s_z[4*i+3];
        }
        s_h[j] = gelu_f(s + pb1[j]);
    }
    __syncthreads();

    // out = h @ pw2^T + pb2
    for (int c = tid; c < NC; c += 256) {
        const float4* wr = (const float4*)(pw2 + (size_t)c * D_);
        float s = 0.f;
        #pragma unroll 8
        for (int i = 0; i < D_ / 4; i++) {
            float4 w = wr[i];
            s += w.x * s_h[4*i] + w.y * s_h[4*i+1] + w.z * s_h[4*i+2] + w.w * s_h[4*i+3];
        }
        out[(size_t)b * NC + c] = s + pb2[c];
    }
}

// =========================================================================
extern "C" void kernel_launch(void* const* d_in, const int* in_sizes, int n_in,
                              void* d_out, int out_size)
{
    const float* x_items = (const float*)d_in[0];
    const float* x_query = (const float*)d_in[1];
    const float* pxw1    = (const float*)d_in[2];
    const float* pxb1    = (const float*)d_in[3];
    const float* pxw2    = (const float*)d_in[4];
    const float* pxb2    = (const float*)d_in[5];
    const float* pqw1    = (const float*)d_in[6];
    const float* pqb1    = (const float*)d_in[7];
    const float* pqw2    = (const float*)d_in[8];
    const float* pqb2    = (const float*)d_in[9];
    const float* qw      = (const float*)d_in[10];
    const float* qb      = (const float*)d_in[11];
    const float* kw      = (const float*)d_in[12];
    const float* kb      = (const float*)d_in[13];
    const float* vw      = (const float*)d_in[14];
    const float* vb      = (const float*)d_in[15];
    const float* pw1     = (const float*)d_in[16];
    const float* pb1     = (const float*)d_in[17];
    const float* pw2     = (const float*)d_in[18];
    const float* pb2     = (const float*)d_in[19];
    float* out = (float*)d_out;

    cudaFuncSetAttribute(k_main, cudaFuncAttributeMaxDynamicSharedMemorySize, SMEM_BYTES);

    k_query<<<B_, D_>>>(x_query, pqw1, pqb1, pqw2, pqb2, qw, qb, kw, kb);
    k_main<<<dim3(NT, B_), 256, SMEM_BYTES>>>(x_items, pxw1, pxb1, pxw2, pxb2);
    k_final<<<B_, NT>>>(vw, vb, pw1, pb1, pw2, pb2, out);
}

// round 2
// speedup vs baseline: 3.6003x; 3.6003x over previous
#include <cuda_runtime.h>
#include <math.h>
#include <stddef.h>

#define B_  32
#define N_  8192
#define DI  128
#define D_  512
#define NC  1000
#define TT  32            // items per tile
#define NT  (N_ / TT)     // 256 tiles per batch

// ---------------- device scratch (static allocation only) ----------------
__device__ float g_P[D_ * D_];           // kw @ w2   (score fold)
__device__ float g_e[D_];                // kw @ b2
__device__ float g_M[D_ * D_];           // vw @ w2   (value fold)
__device__ float g_d[D_];                // vw @ b2 + vb
__device__ float g_u[B_ * D_];           // per-batch score vector (in H1 space)
__device__ float g_c[B_];                // per-batch score constant
__device__ float g_pm[B_ * NT];          // per-tile softmax max
__device__ float g_pl[B_ * NT];          // per-tile softmax sum
__device__ float g_pacc[B_ * NT * D_];   // per-tile weighted H1 accum (16.8 MB)

__device__ __forceinline__ float gelu_f(float x) {
    // exact GELU: 0.5 x (1 + erf(x / sqrt(2)))
    return 0.5f * x * (1.0f + erff(x * 0.70710678118654752440f));
}

// =========================================================================
// Kernel 0: precompute folded weight products (input-independent).
//   blocks 0..63  : P = kw @ w2 rows, e = kw @ b2
//   blocks 64..127: M = vw @ w2 rows, d = vw @ b2 + vb
// grid = 128, block = 256
// =========================================================================
__global__ __launch_bounds__(256) void k_prep(
    const float* __restrict__ kw, const float* __restrict__ w2,
    const float* __restrict__ b2, const float* __restrict__ vw,
    const float* __restrict__ vb)
{
    __shared__ float sA[8][D_];
    const int blk = blockIdx.x;
    const bool isM = blk >= 64;
    const int r0 = (blk & 63) * 8;
    const float* A = isM ? vw : kw;
    const int tid = threadIdx.x;

    for (int e = tid; e < 8 * (D_ / 4); e += 256) {
        int r = e / (D_ / 4), c = e % (D_ / 4);
        ((float4*)sA[r])[c] = ((const float4*)(A + (size_t)(r0 + r) * D_))[c];
    }
    __syncthreads();

    float* OUT = isM ? g_M : g_P;
    for (int j = tid; j < D_; j += 256) {
        float acc[8] = {};
        #pragma unroll 4
        for (int k = 0; k < D_; k++) {
            float wv = w2[(size_t)k * D_ + j];
            #pragma unroll
            for (int r = 0; r < 8; r++) acc[r] = fmaf(sA[r][k], wv, acc[r]);
        }
        #pragma unroll
        for (int r = 0; r < 8; r++) OUT[(size_t)(r0 + r) * D_ + j] = acc[r];
    }
    if (tid < 8) {
        float s = 0.f;
        #pragma unroll 8
        for (int k = 0; k < D_; k++) s = fmaf(sA[tid][k], b2[k], s);
        if (isM) g_d[r0 + tid] = s + vb[r0 + tid];
        else     g_e[r0 + tid] = s;
    }
}

// =========================================================================
// Kernel 1: query path. h_q MLP -> q -> u = P^T q, c = q.(e + k_b).
// grid = B_, block = 512
// =========================================================================
__global__ __launch_bounds__(512) void k_query(
    const float* __restrict__ x_query,
    const float* __restrict__ w1, const float* __restrict__ b1,   // psi_q_w1 [512,1], b1 [512]
    const float* __restrict__ w2, const float* __restrict__ b2,   // psi_q_w2 [512,512]
    const float* __restrict__ qw, const float* __restrict__ qb,   // q_w [512,512]
    const float* __restrict__ kb)                                  // k_b [512]
{
    __shared__ float h1[D_], h2[D_], qv[D_];
    __shared__ float red[16];
    const int b = blockIdx.x;
    const int j = threadIdx.x;

    const float xq = x_query[b];
    h1[j] = gelu_f(fmaf(xq, w1[j], b1[j]));
    __syncthreads();

    {
        const float4* wr = (const float4*)(w2 + (size_t)j * D_);
        float s = 0.f;
        #pragma unroll 8
        for (int i = 0; i < D_ / 4; i++) {
            float4 w = wr[i];
            s += w.x * h1[4*i] + w.y * h1[4*i+1] + w.z * h1[4*i+2] + w.w * h1[4*i+3];
        }
        h2[j] = s + b2[j];
    }
    __syncthreads();
    {
        const float4* wr = (const float4*)(qw + (size_t)j * D_);
        float s = 0.f;
        #pragma unroll 8
        for (int i = 0; i < D_ / 4; i++) {
            float4 w = wr[i];
            s += w.x * h2[4*i] + w.y * h2[4*i+1] + w.z * h2[4*i+2] + w.w * h2[4*i+3];
        }
        qv[j] = s + qb[j];
    }
    __syncthreads();

    // u[b][j] = sum_m qv[m] * P[m*512 + j]   (coalesced over j)
    {
        float s = 0.f;
        #pragma unroll 8
        for (int m = 0; m < D_; m++) s = fmaf(qv[m], g_P[(size_t)m * D_ + j], s);
        g_u[b * D_ + j] = s;
    }
    // c = qv . (e + kb)
    {
        float p = qv[j] * (g_e[j] + kb[j]);
        for (int o = 16; o; o >>= 1) p += __shfl_down_sync(0xffffffffu, p, o);
        if ((j & 31) == 0) red[j >> 5] = p;
        __syncthreads();
        if (j == 0) {
            float t = 0.f;
            for (int i = 0; i < 16; i++) t += red[i];
            g_c[b] = t;
        }
    }
}

// =========================================================================
// Kernel 2: fused item MLP layer-1 + score + per-tile softmax partials.
// grid = (NT, B_), block = 256, dynamic smem.
// =========================================================================
#define XT_STRIDE 36    // k-major A tile stride (32 items padded)
#define W_STRIDE  132   // staged weight tile stride (128 cols padded)
#define H1_STRIDE 520   // row-major H1 stride (512 padded)

#define OFF_XT 0                       // 128*36  = 4608
#define OFF_W  4608                    // 32*132  = 4224
#define OFF_H1 (4608 + 4224)           // 8832; 32*520 = 16640
#define OFF_S  (8832 + 16640)          // 25472; 32 scores
#define OFF_P  (25472 + 32)            // 25504; 32 probs
#define SMEM_FLOATS 25540
#define SMEM_BYTES (SMEM_FLOATS * 4)

// C[32 x 512] = act(A[KD x 32 k-major] . W[512 x KD]^T + bias), row-major out
// thread layout: tx = tid&31 (4 cols each), ty = tid>>5 (4 rows each)
__device__ __forceinline__ void gemm_tile(
    const float* __restrict__ sA, int KD,
    const float* __restrict__ W, const float* __restrict__ bias,
    bool act, float* sW, float* out,
    int tid, int tx, int ty)
{
    for (int j0 = 0; j0 < D_; j0 += 128) {
        float acc[4][4] = {};
        for (int k0 = 0; k0 < KD; k0 += 32) {
            __syncthreads();
            // stage sW[kk][jj] = W[(j0+jj)*KD + k0 + kk], jj<128, kk<32
            #pragma unroll
            for (int it = 0; it < 4; it++) {
                int e  = it * 256 + tid;   // 0..1023
                int jj = e >> 3;
                int kq = e & 7;
                float4 v = *(const float4*)(W + (size_t)(j0 + jj) * KD + k0 + kq * 4);
                int kk = kq * 4;
                sW[(kk + 0) * W_STRIDE + jj] = v.x;
                sW[(kk + 1) * W_STRIDE + jj] = v.y;
                sW[(kk + 2) * W_STRIDE + jj] = v.z;
                sW[(kk + 3) * W_STRIDE + jj] = v.w;
            }
            __syncthreads();
            const float* Ap = sA + (size_t)k0 * XT_STRIDE + ty * 4;
            const float* Wp = sW + tx * 4;
            #pragma unroll
            for (int kk = 0; kk < 32; kk++) {
                float4 a = *(const float4*)(Ap + kk * XT_STRIDE);
                float4 w = *(const float4*)(Wp + kk * W_STRIDE);
                acc[0][0] = fmaf(a.x, w.x, acc[0][0]);
                acc[0][1] = fmaf(a.x, w.y, acc[0][1]);
                acc[0][2] = fmaf(a.x, w.z, acc[0][2]);
                acc[0][3] = fmaf(a.x, w.w, acc[0][3]);
                acc[1][0] = fmaf(a.y, w.x, acc[1][0]);
                acc[1][1] = fmaf(a.y, w.y, acc[1][1]);
                acc[1][2] = fmaf(a.y, w.z, acc[1][2]);
                acc[1][3] = fmaf(a.y, w.w, acc[1][3]);
                acc[2][0] = fmaf(a.z, w.x, acc[2][0]);
                acc[2][1] = fmaf(a.z, w.y, acc[2][1]);
                acc[2][2] = fmaf(a.z, w.z, acc[2][2]);
                acc[2][3] = fmaf(a.z, w.w, acc[2][3]);
                acc[3][0] = fmaf(a.w, w.x, acc[3][0]);
                acc[3][1] = fmaf(a.w, w.y, acc[3][1]);
                acc[3][2] = fmaf(a.w, w.z, acc[3][2]);
                acc[3][3] = fmaf(a.w, w.w, acc[3][3]);
            }
        }
        float bv[4];
        #pragma unroll
        for (int c = 0; c < 4; c++) bv[c] = bias[j0 + tx * 4 + c];
        #pragma unroll
        for (int r = 0; r < 4; r++)
            #pragma unroll
            for (int c = 0; c < 4; c++) {
                float v = acc[r][c] + bv[c];
                acc[r][c] = act ? gelu_f(v) : v;
            }
        #pragma unroll
        for (int r = 0; r < 4; r++) {
            int t = ty * 4 + r;
            float4 v = make_float4(acc[r][0], acc[r][1], acc[r][2], acc[r][3]);
            *(float4*)(out + (size_t)t * H1_STRIDE + j0 + tx * 4) = v;
        }
    }
}

__global__ __launch_bounds__(256, 2) void k_main(
    const float* __restrict__ x_items,
    const float* __restrict__ w1, const float* __restrict__ b1)   // psi_x_w1 [512,128]
{
    extern __shared__ float sm[];
    float* sXt = sm + OFF_XT;
    float* sW  = sm + OFF_W;
    float* sH1 = sm + OFF_H1;
    float* sS  = sm + OFF_S;
    float* sP  = sm + OFF_P;

    const int tile = blockIdx.x;
    const int b    = blockIdx.y;
    const int tid  = threadIdx.x;
    const int tx   = tid & 31;
    const int ty   = tid >> 5;
    const int n0   = tile * TT;

    // load X tile transposed: sXt[i][t]
    {
        const float4* src = (const float4*)(x_items + ((size_t)b * N_ + n0) * DI);
        #pragma unroll
        for (int it = 0; it < 4; it++) {
            int e  = it * 256 + tid;         // 0..1023 of 32*32 float4s
            int t  = e >> 5;
            int iq = e & 31;
            float4 v = src[t * (DI / 4) + iq];
            int i0 = iq * 4;
            sXt[(i0 + 0) * XT_STRIDE + t] = v.x;
            sXt[(i0 + 1) * XT_STRIDE + t] = v.y;
            sXt[(i0 + 2) * XT_STRIDE + t] = v.z;
            sXt[(i0 + 3) * XT_STRIDE + t] = v.w;
        }
    }
    // (gemm_tile syncs before first staging, covering sXt writes)

    // H1 = gelu(X @ W1^T + b1)   -> row-major in sH1
    gemm_tile(sXt, DI, w1, b1, true, sW, sH1, tid, tx, ty);
    __syncthreads();

    // scores: s[t] = (H1[t] . u[b] + c[b]) / sqrt(512)
    {
        int t  = tid >> 3;
        int l8 = tid & 7;
        const float* up  = g_u + b * D_;
        const float* row = sH1 + (size_t)t * H1_STRIDE;
        float s = 0.f;
        int j0 = l8 * 64;
        #pragma unroll
        for (int j = 0; j < 64; j += 4) {
            float4 hv = *(const float4*)(row + j0 + j);
            float4 uv = *(const float4*)(up + j0 + j);
            s += hv.x * uv.x + hv.y * uv.y + hv.z * uv.z + hv.w * uv.w;
        }
        s += __shfl_down_sync(0xffffffffu, s, 4);
        s += __shfl_down_sync(0xffffffffu, s, 2);
        s += __shfl_down_sync(0xffffffffu, s, 1);
        if (l8 == 0) sS[t] = (s + g_c[b]) * 0.044194173824159216f;  // 512^-0.5
    }
    __syncthreads();

    // per-tile softmax partials (warp 0)
    if (tid < 32) {
        float sv = sS[tid];
        float m = sv;
        for (int o = 16; o; o >>= 1) m = fmaxf(m, __shfl_xor_sync(0xffffffffu, m, o));
        float p = expf(sv - m);
        float l = p;
        for (int o = 16; o; o >>= 1) l += __shfl_xor_sync(0xffffffffu, l, o);
        sP[tid] = p;
        if (tid == 0) {
            g_pm[b * NT + tile] = m;
            g_pl[b * NT + tile] = l;
        }
    }
    __syncthreads();

    // weighted accumulate in H1 space: acc[j] = sum_t p[t] * H1[t][j]
    {
        float* dst = g_pacc + ((size_t)(b * NT + tile)) * D_;
        #pragma unroll
        for (int j = tid; j < D_; j += 256) {
            float a = 0.f;
            #pragma unroll
            for (int t = 0; t < TT; t++) a = fmaf(sP[t], sH1[(size_t)t * H1_STRIDE + j], a);
            dst[j] = a;
        }
    }
}

// =========================================================================
// Kernel 3: combine tile partials, folded (Wv*W2) projection, phi MLP, out.
// grid = B_, block = NT (256)
// =========================================================================
__global__ __launch_bounds__(256) void k_final(
    const float* __restrict__ pw1, const float* __restrict__ pb1,
    const float* __restrict__ pw2, const float* __restrict__ pb2,
    float* __restrict__ out)
{
    __shared__ float s_scale[NT];
    __shared__ float s_zh[D_];
    __shared__ float s_z[D_];
    __shared__ float s_h[D_];
    __shared__ float s_red[8];
    __shared__ float s_M, s_L;

    const int b   = blockIdx.x;
    const int tid = threadIdx.x;
    const int lane = tid & 31, warp = tid >> 5;

    const float m = g_pm[b * NT + tid];
    // block max
    float mw = m;
    for (int o = 16; o; o >>= 1) mw = fmaxf(mw, __shfl_xor_sync(0xffffffffu, mw, o));
    if (lane == 0) s_red[warp] = mw;
    __syncthreads();
    if (tid == 0) {
        float t = s_red[0];
        for (int i = 1; i < 8; i++) t = fmaxf(t, s_red[i]);
        s_M = t;
    }
    __syncthreads();
    const float M = s_M;
    const float sc = expf(m - M);
    s_scale[tid] = sc;
    // block sum of l_i * scale_i
    float lp = g_pl[b * NT + tid] * sc;
    for (int o = 16; o; o >>= 1) lp += __shfl_xor_sync(0xffffffffu, lp, o);
    __syncthreads();
    if (lane == 0) s_red[warp] = lp;
    __syncthreads();
    if (tid == 0) {
        float t = 0.f;
        for (int i = 0; i < 8; i++) t += s_red[i];
        s_L = t;
    }
    __syncthreads();
    const float invL = 1.0f / s_L;

    // zh[j] = H1_bar[j] = sum_i acc[i][j] * scale_i / L
    for (int j = tid; j < D_; j += 256) {
        const float* base = g_pacc + ((size_t)b * NT) * D_ + j;
        float s = 0.f;
        #pragma unroll 8
        for (int i = 0; i < NT; i++) s = fmaf(base[(size_t)i * D_], s_scale[i], s);
        s_zh[j] = s * invL;
    }
    __syncthreads();

    // z = M_fold @ zh + d   (M_fold = vw @ w2, d = vw @ b2 + vb)
    for (int j = tid; j < D_; j += 256) {
        const float4* wr = (const float4*)(g_M + (size_t)j * D_);
        float s = 0.f;
        #pragma unroll 8
        for (int i = 0; i < D_ / 4; i++) {
            float4 w = wr[i];
            s += w.x * s_zh[4*i] + w.y * s_zh[4*i+1] + w.z * s_zh[4*i+2] + w.w * s_zh[4*i+3];
        }
        s_z[j] = s + g_d[j];
    }
    __syncthreads();

    // h = gelu(z @ pw1^T + pb1)
    for (int j = tid; j < D_; j += 256) {
        const float4* wr = (const float4*)(pw1 + (size_t)j * D_);
        float s = 0.f;
        #pragma unroll 8
        for (int i = 0; i < D_ / 4; i++) {
            float4 w = wr[i];
            s += w.x * s_z[4*i] + w.y * s_z[4*i+1] + w.z * s_z[4*i+2] + w.w * s_z[4*i+3];
        }
        s_h[j] = gelu_f(s + pb1[j]);
    }
    __syncthreads();

    // out = h @ pw2^T + pb2
    for (int c = tid; c < NC; c += 256) {
        const float4* wr = (const float4*)(pw2 + (size_t)c * D_);
        float s = 0.f;
        #pragma unroll 8
        for (int i = 0; i < D_ / 4; i++) {
            float4 w = wr[i];
            s += w.x * s_h[4*i] + w.y * s_h[4*i+1] + w.z * s_h[4*i+2] + w.w * s_h[4*i+3];
        }
        out[(size_t)b * NC + c] = s + pb2[c];
    }
}

// =========================================================================
extern "C" void kernel_launch(void* const* d_in, const int* in_sizes, int n_in,
                              void* d_out, int out_size)
{
    const float* x_items = (const float*)d_in[0];
    const float* x_query = (const float*)d_in[1];
    const float* pxw1    = (const float*)d_in[2];
    const float* pxb1    = (const float*)d_in[3];
    const float* pxw2    = (const float*)d_in[4];
    const float* pxb2    = (const float*)d_in[5];
    const float* pqw1    = (const float*)d_in[6];
    const float* pqb1    = (const float*)d_in[7];
    const float* pqw2    = (const float*)d_in[8];
    const float* pqb2    = (const float*)d_in[9];
    const float* qw      = (const float*)d_in[10];
    const float* qb      = (const float*)d_in[11];
    const float* kw      = (const float*)d_in[12];
    const float* kb      = (const float*)d_in[13];
    const float* vw      = (const float*)d_in[14];
    const float* vb      = (const float*)d_in[15];
    const float* pw1     = (const float*)d_in[16];
    const float* pb1     = (const float*)d_in[17];
    const float* pw2     = (const float*)d_in[18];
    const float* pb2     = (const float*)d_in[19];
    float* out = (float*)d_out;

    cudaFuncSetAttribute(k_main, cudaFuncAttributeMaxDynamicSharedMemorySize, SMEM_BYTES);

    // folded weight products (input-independent but cheap: ~270 MMAC)
    k_prep<<<128, 256>>>(kw, pxw2, pxb2, vw, vb);
    // query path -> u, c (needs g_P, g_e)
    k_query<<<B_, D_>>>(x_query, pqw1, pqb1, pqw2, pqb2, qw, qb, kb);
    // fused item layer-1 MLP + attention partials
    k_main<<<dim3(NT, B_), 256, SMEM_BYTES>>>(x_items, pxw1, pxb1);
    // combine + folded value projection + phi MLP
    k_final<<<B_, NT>>>(pw1, pb1, pw2, pb2, out);
}

// round 11
// speedup vs baseline: 5.1658x; 1.4348x over previous
#include <cuda_runtime.h>
#include <cuda_bf16.h>
#include <cuda_fp16.h>
#include <math.h>
#include <stddef.h>
#include <stdint.h>

#define B_  32
#define N_  8192
#define DI  128
#define D_  512
#define NC  1000
#define TM  64            // items per tile
#define NT3 128           // tiles per batch

// ---------------- device scratch (static allocation only) ----------------
__device__ float g_P[D_ * D_];           // kw @ w2   (score fold)
__device__ float g_e[D_];                // kw @ b2
__device__ float g_M[D_ * D_];           // vw @ w2   (value fold)
__device__ float g_d[D_];                // vw @ b2 + vb
__device__ float g_u[B_ * D_];           // per-batch score vector (H1 space)
__device__ float g_c[B_];                // per-batch score constant
__device__ float g_pm[B_ * NT3];         // per-tile softmax max
__device__ float g_pl[B_ * NT3];         // per-tile softmax sum
__device__ float g_pacc[B_ * NT3 * D_];  // per-tile weighted H1 accum (8.4 MB)
__device__ __align__(16) float2 g_w1s[D_ * DI];  // W1 tf32 split (hi, lo)

__device__ __forceinline__ float gelu_f(float x) {
    return 0.5f * x * (1.0f + erff(x * 0.70710678118654752440f));
}
__device__ __forceinline__ uint32_t smem_u32(const void* p) {
    uint32_t a;
    asm("{ .reg .u64 t; cvta.to.shared.u64 t, %1; cvt.u32.u64 %0, t; }" : "=r"(a) : "l"(p));
    return a;
}
__device__ __forceinline__ float f2tf(float x) {
    uint32_t r;
    asm("cvt.rna.tf32.f32 %0, %1;" : "=r"(r) : "f"(x));
    return __uint_as_float(r);
}
__device__ __forceinline__ float2 tf_split(float x) {
    float h = f2tf(x);
    return make_float2(h, f2tf(x - h));
}
__device__ __forceinline__ void mma_tf32(float* c, const uint32_t* a, uint32_t b0, uint32_t b1) {
    asm volatile("mma.sync.aligned.m16n8k8.row.col.f32.tf32.tf32.f32 "
        "{%0,%1,%2,%3}, {%4,%5,%6,%7}, {%8,%9}, {%0,%1,%2,%3};"
        : "+f"(c[0]), "+f"(c[1]), "+f"(c[2]), "+f"(c[3])
        : "r"(a[0]), "r"(a[1]), "r"(a[2]), "r"(a[3]), "r"(b0), "r"(b1));
}
#define FAU(x) __float_as_uint(x)
#define CP_ASYNC16(dst, src) asm volatile("cp.async.cg.shared.global [%0], [%1], 16;" :: "r"(dst), "l"(src) : "memory")
#define CP_COMMIT()          asm volatile("cp.async.commit_group;" ::: "memory")
#define CP_WAIT0()           asm volatile("cp.async.wait_group 0;" ::: "memory")

// ---------------- k_main SMEM layout ----------------
#define AS2F 132                        // float2 per row (128 data + 4 pad)
#define ROWB (AS2F * 8)                 // 1056 bytes per row
#define OFF_A   0                       // 64*1056 = 67584
#define OFF_W   67584                   // 64*1056 = 67584 -> 135168
#define H1S 1040                        // fp16 H1 row stride (bytes)
#define OFF_H1  135168                  // 64*1040 = 66560 -> 201728
#define OFF_U   201728                  // 512 floats
#define OFF_B1  203776                  // 512 floats
#define OFF_SP  205824                  // 128 floats
#define OFF_PR  206336                  // 64 floats
#define SMEM_MAIN 206656

// =========================================================================
// k_conv: tf32-split W1 -> float2(hi, lo). grid=256, block=256
// =========================================================================
__global__ __launch_bounds__(256) void k_conv(const float* __restrict__ w1) {
    int i = blockIdx.x * 256 + threadIdx.x;
    g_w1s[i] = tf_split(w1[i]);
}

// =========================================================================
// k_prep: folded weight products (verbatim from passing round-2 kernel).
// grid=128, block=256
// =========================================================================
__global__ __launch_bounds__(256) void k_prep(
    const float* __restrict__ kw, const float* __restrict__ w2,
    const float* __restrict__ b2, const float* __restrict__ vw,
    const float* __restrict__ vb)
{
    __shared__ float sA[8][D_];
    const int blk = blockIdx.x;
    const bool isM = blk >= 64;
    const int r0 = (blk & 63) * 8;
    const float* A = isM ? vw : kw;
    const int tid = threadIdx.x;

    for (int e = tid; e < 8 * (D_ / 4); e += 256) {
        int r = e / (D_ / 4), c = e % (D_ / 4);
        ((float4*)sA[r])[c] = ((const float4*)(A + (size_t)(r0 + r) * D_))[c];
    }
    __syncthreads();

    float* OUT = isM ? g_M : g_P;
    for (int j = tid; j < D_; j += 256) {
        float acc[8] = {};
        #pragma unroll 4
        for (int k = 0; k < D_; k++) {
            float wv = w2[(size_t)k * D_ + j];
            #pragma unroll
            for (int r = 0; r < 8; r++) acc[r] = fmaf(sA[r][k], wv, acc[r]);
        }
        #pragma unroll
        for (int r = 0; r < 8; r++) OUT[(size_t)(r0 + r) * D_ + j] = acc[r];
    }
    if (tid < 8) {
        float s = 0.f;
        #pragma unroll 8
        for (int k = 0; k < D_; k++) s = fmaf(sA[tid][k], b2[k], s);
        if (isM) g_d[r0 + tid] = s + vb[r0 + tid];
        else     g_e[r0 + tid] = s;
    }
}

// =========================================================================
// k_query: monolithic query path (verbatim from passing round-2 kernel).
// grid = B_, block = 512
// =========================================================================
__global__ __launch_bounds__(512) void k_query(
    const float* __restrict__ x_query,
    const float* __restrict__ w1, const float* __restrict__ b1,
    const float* __restrict__ w2, const float* __restrict__ b2,
    const float* __restrict__ qw, const float* __restrict__ qb,
    const float* __restrict__ kb)
{
    __shared__ float h1[D_], h2[D_], qv[D_];
    __shared__ float red[16];
    const int b = blockIdx.x;
    const int j = threadIdx.x;

    const float xq = x_query[b];
    h1[j] = gelu_f(fmaf(xq, w1[j], b1[j]));
    __syncthreads();

    {
        const float4* wr = (const float4*)(w2 + (size_t)j * D_);
        float s = 0.f;
        #pragma unroll 8
        for (int i = 0; i < D_ / 4; i++) {
            float4 w = wr[i];
            s += w.x * h1[4*i] + w.y * h1[4*i+1] + w.z * h1[4*i+2] + w.w * h1[4*i+3];
        }
        h2[j] = s + b2[j];
    }
    __syncthreads();
    {
        const float4* wr = (const float4*)(qw + (size_t)j * D_);
        float s = 0.f;
        #pragma unroll 8
        for (int i = 0; i < D_ / 4; i++) {
            float4 w = wr[i];
            s += w.x * h2[4*i] + w.y * h2[4*i+1] + w.z * h2[4*i+2] + w.w * h2[4*i+3];
        }
        qv[j] = s + qb[j];
    }
    __syncthreads();

    // u[b][j] = sum_m qv[m] * P[m*512 + j]   (coalesced over j)
    {
        float s = 0.f;
        #pragma unroll 8
        for (int m = 0; m < D_; m++) s = fmaf(qv[m], g_P[(size_t)m * D_ + j], s);
        g_u[b * D_ + j] = s;
    }
    // c = qv . (e + kb)
    {
        float p = qv[j] * (g_e[j] + kb[j]);
        for (int o = 16; o; o >>= 1) p += __shfl_down_sync(0xffffffffu, p, o);
        if ((j & 31) == 0) red[j >> 5] = p;
        __syncthreads();
        if (j == 0) {
            float t = 0.f;
            for (int i = 0; i < 16; i++) t += red[i];
            g_c[b] = t;
        }
    }
}

// =========================================================================
// k_main: split-tf32 MMA GEMM1 + gelu + scores + softmax partials.
// (verbatim round-9 version)
// grid=(NT3, B_), block=256 (8 warps: 4 item groups x 2 dim halves)
// =========================================================================
__device__ __forceinline__ void load_w_chunk(int c, uint32_t sb, int tid) {
    #pragma unroll
    for (int it = 0; it < 16; ++it) {
        int e = it * 256 + tid;          // 0..4095
        int r = e >> 6, sg = e & 63;
        uint32_t dst = sb + OFF_W + r * ROWB + sg * 16;
        const float2* src = g_w1s + (size_t)(c * 64 + r) * DI + sg * 2;
        CP_ASYNC16(dst, src);
    }
}

__global__ __launch_bounds__(256, 1) void k_main(
    const float* __restrict__ x_items,
    const float* __restrict__ b1)
{
    extern __shared__ char sm[];
    const uint32_t sb = smem_u32(sm);
    const int tile = blockIdx.x;
    const int b    = blockIdx.y;
    const int tid  = threadIdx.x;
    const int wid  = tid >> 5;
    const int lane = tid & 31;
    const int mw   = wid & 3;            // item group (16 items)
    const int nh   = wid >> 2;           // dim half (32 dims within 64-chunk)
    const int n0   = tile * TM;
    const int q    = lane >> 2, t4 = lane & 3;

    float* su  = (float*)(sm + OFF_U);
    float* sb1 = (float*)(sm + OFF_B1);
    float* sp  = (float*)(sm + OFF_SP);
    float* spr = (float*)(sm + OFF_PR);
    float2* Af = (float2*)(sm + OFF_A);
    float2* Wf = (float2*)(sm + OFF_W);

    for (int j = tid; j < D_; j += 256) { su[j] = g_u[b * D_ + j]; sb1[j] = b1[j]; }

    // stage X tile -> tf32-split float2(hi, lo), row-major 132-float2 stride
    {
        const float4* xs = (const float4*)(x_items + ((size_t)b * N_ + n0) * DI);
        #pragma unroll
        for (int it = 0; it < 8; ++it) {
            int e = it * 256 + tid;        // 64 items x 32 quads
            int i = e >> 5, qd = e & 31;
            float4 v = xs[i * 32 + qd];
            float2* dst = Af + i * AS2F + qd * 4;
            dst[0] = tf_split(v.x);
            dst[1] = tf_split(v.y);
            dst[2] = tf_split(v.z);
            dst[3] = tf_split(v.w);
        }
    }
    load_w_chunk(0, sb, tid);
    CP_COMMIT();

    const int ra = (mw * 16 + q) * AS2F;
    const int rb = (nh * 32 + q) * AS2F;

    float s0 = 0.f, s1 = 0.f;     // score partials for rows mw*16+q and +8

    for (int c = 0; c < 8; ++c) {
        CP_WAIT0();
        __syncthreads();           // W[c] staged, A visible (c==0)

        float acc[4][4] = {};
        #pragma unroll
        for (int ks = 0; ks < 16; ++ks) {
            const int kk = ks * 8 + t4;
            float2 A0 = Af[ra + kk];
            float2 A1 = Af[ra + 8 * AS2F + kk];
            float2 A2 = Af[ra + kk + 4];
            float2 A3 = Af[ra + 8 * AS2F + kk + 4];
            uint32_t ah[4] = {FAU(A0.x), FAU(A1.x), FAU(A2.x), FAU(A3.x)};
            uint32_t al[4] = {FAU(A0.y), FAU(A1.y), FAU(A2.y), FAU(A3.y)};
            #pragma unroll
            for (int nb = 0; nb < 4; ++nb) {
                float2 B0 = Wf[rb + nb * 8 * AS2F + kk];
                float2 B1 = Wf[rb + nb * 8 * AS2F + kk + 4];
                mma_tf32(acc[nb], ah, FAU(B0.x), FAU(B1.x));   // Xh*Wh
                mma_tf32(acc[nb], ah, FAU(B0.y), FAU(B1.y));   // Xh*Wl
                mma_tf32(acc[nb], al, FAU(B0.x), FAU(B1.x));   // Xl*Wh
            }
        }
        __syncthreads();           // all warps done reading W[c]
        if (c < 7) {               // prefetch next W; overlaps with epilogue
            load_w_chunk(c + 1, sb, tid);
            CP_COMMIT();
        }

        // epilogue for this 64-dim chunk (fp16 H1)
        const int jb = c * 64 + nh * 32;
        const int r0 = mw * 16 + q;
        char* h1p = sm + OFF_H1;
        #pragma unroll
        for (int nb = 0; nb < 4; ++nb) {
            int j0 = jb + nb * 8 + t4 * 2;
            float b0v = sb1[j0], b1v = sb1[j0 + 1];
            float u0 = su[j0], u1 = su[j0 + 1];
            float h00 = gelu_f(acc[nb][0] + b0v);
            float h01 = gelu_f(acc[nb][1] + b1v);
            float h10 = gelu_f(acc[nb][2] + b0v);
            float h11 = gelu_f(acc[nb][3] + b1v);
            s0 = fmaf(h00, u0, fmaf(h01, u1, s0));
            s1 = fmaf(h10, u0, fmaf(h11, u1, s1));
            *(__half2*)(h1p + r0 * H1S + j0 * 2)       = __floats2half2_rn(h00, h01);
            *(__half2*)(h1p + (r0 + 8) * H1S + j0 * 2) = __floats2half2_rn(h10, h11);
        }
    }

    // score reduction: sum over t4 lanes
    s0 += __shfl_xor_sync(0xffffffffu, s0, 1);
    s0 += __shfl_xor_sync(0xffffffffu, s0, 2);
    s1 += __shfl_xor_sync(0xffffffffu, s1, 1);
    s1 += __shfl_xor_sync(0xffffffffu, s1, 2);
    if (t4 == 0) {
        sp[nh * 64 + mw * 16 + q]     = s0;
        sp[nh * 64 + mw * 16 + q + 8] = s1;
    }
    __syncthreads();

    // softmax over 64 items (warp 0)
    if (wid == 0) {
        const float cb = g_c[b];
        float v0 = (sp[lane] + sp[64 + lane] + cb) * 0.044194173824159216f;
        float v1 = (sp[32 + lane] + sp[96 + lane] + cb) * 0.044194173824159216f;
        float m = fmaxf(v0, v1);
        for (int o = 16; o; o >>= 1) m = fmaxf(m, __shfl_xor_sync(0xffffffffu, m, o));
        float p0 = expf(v0 - m), p1 = expf(v1 - m);
        float l = p0 + p1;
        for (int o = 16; o; o >>= 1) l += __shfl_xor_sync(0xffffffffu, l, o);
        spr[lane] = p0;
        spr[lane + 32] = p1;
        if (lane == 0) {
            g_pm[b * NT3 + tile] = m;
            g_pl[b * NT3 + tile] = l;
        }
    }
    __syncthreads();

    // pacc[dim] = sum_items p[i] * H1[i][dim]; thread handles dims 2*tid, +1
    {
        const char* h1p = sm + OFF_H1;
        float ax = 0.f, ay = 0.f;
        #pragma unroll 8
        for (int i = 0; i < TM; ++i) {
            float2 h = __half22float2(*(const __half2*)(h1p + i * H1S + tid * 4));
            float p = spr[i];
            ax = fmaf(p, h.x, ax);
            ay = fmaf(p, h.y, ay);
        }
        float2* dst = (float2*)(g_pacc + ((size_t)(b * NT3 + tile)) * D_) + tid;
        *dst = make_float2(ax, ay);
    }
}

// =========================================================================
// k_final: combine tile partials, folded V proj, phi MLP.
// (round-2 structure, adapted 256 -> 128 tiles; block = 256)
// =========================================================================
__global__ __launch_bounds__(256) void k_final(
    const float* __restrict__ pw1, const float* __restrict__ pb1,
    const float* __restrict__ pw2, const float* __restrict__ pb2,
    float* __restrict__ out)
{
    __shared__ float s_scale[NT3];
    __shared__ float s_zh[D_], s_z[D_], s_h[D_];
    __shared__ float s_red[8];
    __shared__ float s_M, s_L;

    const int b   = blockIdx.x;
    const int tid = threadIdx.x;
    const int lane = tid & 31, warp = tid >> 5;

    const float m = (tid < NT3) ? g_pm[b * NT3 + tid] : -3e38f;
    // block max (warps 4..7 contribute -inf)
    float mw = m;
    for (int o = 16; o; o >>= 1) mw = fmaxf(mw, __shfl_xor_sync(0xffffffffu, mw, o));
    if (lane == 0) s_red[warp] = mw;
    __syncthreads();
    if (tid == 0) {
        float t = s_red[0];
        for (int i = 1; i < 8; i++) t = fmaxf(t, s_red[i]);
        s_M = t;
    }
    __syncthreads();
    const float M = s_M;
    const float sc = expf(m - M);
    if (tid < NT3) s_scale[tid] = sc;
    // block sum of l_i * scale_i
    float lp = (tid < NT3) ? g_pl[b * NT3 + tid] * sc : 0.f;
    for (int o = 16; o; o >>= 1) lp += __shfl_xor_sync(0xffffffffu, lp, o);
    __syncthreads();
    if (lane == 0) s_red[warp] = lp;
    __syncthreads();
    if (tid == 0) {
        float t = 0.f;
        for (int i = 0; i < 8; i++) t += s_red[i];
        s_L = t;
    }
    __syncthreads();
    const float invL = 1.0f / s_L;

    // zh[j] = H1_bar[j] = sum_i acc[i][j] * scale_i / L
    for (int j = tid; j < D_; j += 256) {
        const float* base = g_pacc + ((size_t)b * NT3) * D_ + j;
        float s = 0.f;
        #pragma unroll 8
        for (int i = 0; i < NT3; i++) s = fmaf(base[(size_t)i * D_], s_scale[i], s);
        s_zh[j] = s * invL;
    }
    __syncthreads();

    // z = M_fold @ zh + d
    for (int j = tid; j < D_; j += 256) {
        const float4* wr = (const float4*)(g_M + (size_t)j * D_);
        float s = 0.f;
        #pragma unroll 8
        for (int i = 0; i < D_ / 4; i++) {
            float4 w = wr[i];
            s += w.x * s_zh[4*i] + w.y * s_zh[4*i+1] + w.z * s_zh[4*i+2] + w.w * s_zh[4*i+3];
        }
        s_z[j] = s + g_d[j];
    }
    __syncthreads();

    // h = gelu(z @ pw1^T + pb1)
    for (int j = tid; j < D_; j += 256) {
        const float4* wr = (const float4*)(pw1 + (size_t)j * D_);
        float s = 0.f;
        #pragma unroll 8
        for (int i = 0; i < D_ / 4; i++) {
            float4 w = wr[i];
            s += w.x * s_z[4*i] + w.y * s_z[4*i+1] + w.z * s_z[4*i+2] + w.w * s_z[4*i+3];
        }
        s_h[j] = gelu_f(s + pb1[j]);
    }
    __syncthreads();

    // out = h @ pw2^T + pb2
    for (int c = tid; c < NC; c += 256) {
        const float4* wr = (const float4*)(pw2 + (size_t)c * D_);
        float s = 0.f;
        #pragma unroll 8
        for (int i = 0; i < D_ / 4; i++) {
            float4 w = wr[i];
            s += w.x * s_h[4*i] + w.y * s_h[4*i+1] + w.z * s_h[4*i+2] + w.w * s_h[4*i+3];
        }
        out[(size_t)b * NC + c] = s + pb2[c];
    }
}

// =========================================================================
extern "C" void kernel_launch(void* const* d_in, const int* in_sizes, int n_in,
                              void* d_out, int out_size)
{
    const float* x_items = (const float*)d_in[0];
    const float* x_query = (const float*)d_in[1];
    const float* pxw1    = (const float*)d_in[2];
    const float* pxb1    = (const float*)d_in[3];
    const float* pxw2    = (const float*)d_in[4];
    const float* pxb2    = (const float*)d_in[5];
    const float* pqw1    = (const float*)d_in[6];
    const float* pqb1    = (const float*)d_in[7];
    const float* pqw2    = (const float*)d_in[8];
    const float* pqb2    = (const float*)d_in[9];
    const float* qw      = (const float*)d_in[10];
    const float* qb      = (const float*)d_in[11];
    const float* kw      = (const float*)d_in[12];
    const float* kb      = (const float*)d_in[13];
    const float* vw      = (const float*)d_in[14];
    const float* vb      = (const float*)d_in[15];
    const float* pw1     = (const float*)d_in[16];
    const float* pb1     = (const float*)d_in[17];
    const float* pw2     = (const float*)d_in[18];
    const float* pb2     = (const float*)d_in[19];
    float* out = (float*)d_out;

    cudaFuncSetAttribute(k_main, cudaFuncAttributeMaxDynamicSharedMemorySize, SMEM_MAIN);

    k_conv<<<256, 256>>>(pxw1);
    k_prep<<<128, 256>>>(kw, pxw2, pxb2, vw, vb);
    k_query<<<B_, D_>>>(x_query, pqw1, pqb1, pqw2, pqb2, qw, qb, kb);
    k_main<<<dim3(NT3, B_), 256, SMEM_MAIN>>>(x_items, pxb1);
    k_final<<<B_, 256>>>(pw1, pb1, pw2, pb2, out);
}

// round 14
// speedup vs baseline: 7.0779x; 1.3701x over previous
#include <cuda_runtime.h>
#include <cuda_bf16.h>
#include <cuda_fp16.h>
#include <math.h>
#include <stddef.h>
#include <stdint.h>

#define B_  32
#define N_  8192
#define DI  128
#define D_  512
#define NC  1000
#define TM  64            // items per tile
#define NT3 128           // tiles per batch

// ---------------- device scratch (static allocation only) ----------------
__device__ float g_P[D_ * D_];           // kw @ w2   (score fold)
__device__ float g_e[D_];                // kw @ b2
__device__ float g_M[D_ * D_];           // vw @ w2   (value fold)
__device__ float g_d[D_];                // vw @ b2 + vb
__device__ float g_u[B_ * D_];           // per-batch score vector (H1 space)
__device__ float g_c[B_];                // per-batch score constant
__device__ float g_pm[B_ * NT3];         // per-tile softmax max
__device__ float g_pl[B_ * NT3];         // per-tile softmax sum
__device__ float g_pacc[B_ * NT3 * D_];  // per-tile weighted H1 accum (8.4 MB)
__device__ __align__(16) __nv_bfloat16 g_w1h[D_ * DI];  // W1 split hi
__device__ __align__(16) __nv_bfloat16 g_w1l[D_ * DI];  // W1 split lo

__device__ __forceinline__ float gelu_f(float x) {
    return 0.5f * x * (1.0f + erff(x * 0.70710678118654752440f));
}
__device__ __forceinline__ uint32_t smem_u32(const void* p) {
    uint32_t a;
    asm("{ .reg .u64 t; cvta.to.shared.u64 t, %1; cvt.u32.u64 %0, t; }" : "=r"(a) : "l"(p));
    return a;
}
__device__ __forceinline__ void ldsm4(uint32_t* r, uint32_t addr) {
    asm volatile("ldmatrix.sync.aligned.m8n8.x4.shared.b16 {%0,%1,%2,%3}, [%4];"
        : "=r"(r[0]), "=r"(r[1]), "=r"(r[2]), "=r"(r[3]) : "r"(addr));
}
__device__ __forceinline__ void mma_bf16(float* c, const uint32_t* a, uint32_t b0, uint32_t b1) {
    asm volatile("mma.sync.aligned.m16n8k16.row.col.f32.bf16.bf16.f32 "
        "{%0,%1,%2,%3}, {%4,%5,%6,%7}, {%8,%9}, {%0,%1,%2,%3};"
        : "+f"(c[0]), "+f"(c[1]), "+f"(c[2]), "+f"(c[3])
        : "r"(a[0]), "r"(a[1]), "r"(a[2]), "r"(a[3]), "r"(b0), "r"(b1));
}
#define CP_ASYNC16(dst, src) asm volatile("cp.async.cg.shared.global [%0], [%1], 16;" :: "r"(dst), "l"(src) : "memory")
#define CP_COMMIT()          asm volatile("cp.async.commit_group;" ::: "memory")
#define CP_WAIT1()           asm volatile("cp.async.wait_group 1;" ::: "memory")
#define CP_WAIT0()           asm volatile("cp.async.wait_group 0;" ::: "memory")

// ---------------- k_main SMEM layout (bytes) ----------------
// A rows (items): 256B data + 16B pad = 272B stride -> conflict-free ldmatrix
#define AS 272
#define A_HALF (TM * AS)              // 17408 (hi or lo)
#define OFF_A   0                      // hi, then lo
#define W_HALF (64 * AS)               // 17408 per chunk half
#define W_BUF  (2 * W_HALF)            // 34816: hi + lo
#define OFF_W  (2 * A_HALF)            // 34816; two buffers
#define H1S 1040                       // fp16 H1 row stride (bytes)
#define OFF_H1 (OFF_W + 2 * W_BUF)     // 104448; 64*1040 = 66560
#define OFF_U  (OFF_H1 + TM * H1S)     // 171008
#define OFF_B1 (OFF_U + 2048)          // 173056
#define OFF_SP (OFF_B1 + 2048)         // 175104; 2*64 floats
#define OFF_PR (OFF_SP + 512)          // 175616; 64 floats
#define SMEM_MAIN (OFF_PR + 256 + 64)

// =========================================================================
// k_conv: split W1 into bf16 hi/lo. grid=256, block=256
// =========================================================================
__global__ __launch_bounds__(256) void k_conv(const float* __restrict__ w1) {
    int i = blockIdx.x * 256 + threadIdx.x;
    float v = w1[i];
    __nv_bfloat16 h = __float2bfloat16(v);
    g_w1h[i] = h;
    g_w1l[i] = __float2bfloat16(v - __bfloat162float(h));
}

// =========================================================================
// k_prep: folded weight products (trusted round-2 version). grid=128, block=256
// =========================================================================
__global__ __launch_bounds__(256) void k_prep(
    const float* __restrict__ kw, const float* __restrict__ w2,
    const float* __restrict__ b2, const float* __restrict__ vw,
    const float* __restrict__ vb)
{
    __shared__ float sA[8][D_];
    const int blk = blockIdx.x;
    const bool isM = blk >= 64;
    const int r0 = (blk & 63) * 8;
    const float* A = isM ? vw : kw;
    const int tid = threadIdx.x;

    for (int e = tid; e < 8 * (D_ / 4); e += 256) {
        int r = e / (D_ / 4), c = e % (D_ / 4);
        ((float4*)sA[r])[c] = ((const float4*)(A + (size_t)(r0 + r) * D_))[c];
    }
    __syncthreads();

    float* OUT = isM ? g_M : g_P;
    for (int j = tid; j < D_; j += 256) {
        float acc[8] = {};
        #pragma unroll 4
        for (int k = 0; k < D_; k++) {
            float wv = w2[(size_t)k * D_ + j];
            #pragma unroll
            for (int r = 0; r < 8; r++) acc[r] = fmaf(sA[r][k], wv, acc[r]);
        }
        #pragma unroll
        for (int r = 0; r < 8; r++) OUT[(size_t)(r0 + r) * D_ + j] = acc[r];
    }
    if (tid < 8) {
        float s = 0.f;
        #pragma unroll 8
        for (int k = 0; k < D_; k++) s = fmaf(sA[tid][k], b2[k], s);
        if (isM) g_d[r0 + tid] = s + vb[r0 + tid];
        else     g_e[r0 + tid] = s;
    }
}

// =========================================================================
// k_query: monolithic query path (trusted round-2 version). grid=B_, block=512
// =========================================================================
__global__ __launch_bounds__(512) void k_query(
    const float* __restrict__ x_query,
    const float* __restrict__ w1, const float* __restrict__ b1,
    const float* __restrict__ w2, const float* __restrict__ b2,
    const float* __restrict__ qw, const float* __restrict__ qb,
    const float* __restrict__ kb)
{
    __shared__ float h1[D_], h2[D_], qv[D_];
    __shared__ float red[16];
    const int b = blockIdx.x;
    const int j = threadIdx.x;

    const float xq = x_query[b];
    h1[j] = gelu_f(fmaf(xq, w1[j], b1[j]));
    __syncthreads();

    {
        const float4* wr = (const float4*)(w2 + (size_t)j * D_);
        float s = 0.f;
        #pragma unroll 8
        for (int i = 0; i < D_ / 4; i++) {
            float4 w = wr[i];
            s += w.x * h1[4*i] + w.y * h1[4*i+1] + w.z * h1[4*i+2] + w.w * h1[4*i+3];
        }
        h2[j] = s + b2[j];
    }
    __syncthreads();
    {
        const float4* wr = (const float4*)(qw + (size_t)j * D_);
        float s = 0.f;
        #pragma unroll 8
        for (int i = 0; i < D_ / 4; i++) {
            float4 w = wr[i];
            s += w.x * h2[4*i] + w.y * h2[4*i+1] + w.z * h2[4*i+2] + w.w * h2[4*i+3];
        }
        qv[j] = s + qb[j];
    }
    __syncthreads();

    {
        float s = 0.f;
        #pragma unroll 8
        for (int m = 0; m < D_; m++) s = fmaf(qv[m], g_P[(size_t)m * D_ + j], s);
        g_u[b * D_ + j] = s;
    }
    {
        float p = qv[j] * (g_e[j] + kb[j]);
        for (int o = 16; o; o >>= 1) p += __shfl_down_sync(0xffffffffu, p, o);
        if ((j & 31) == 0) red[j >> 5] = p;
        __syncthreads();
        if (j == 0) {
            float t = 0.f;
            for (int i = 0; i < 16; i++) t += red[i];
            g_c[b] = t;
        }
    }
}

// =========================================================================
// k_main: split-bf16 HMMA GEMM1 (ldmatrix + cp.async) + gelu + scores +
// softmax partials. grid=(NT3, B_), block=256 (8 warps)
// =========================================================================
__device__ __forceinline__ void load_w_async(int c, uint32_t wbuf, int tid) {
    #pragma unroll
    for (int it = 0; it < 8; ++it) {
        int e = it * 256 + tid;          // 0..2047
        int r = e >> 5, u = e & 31;
        int isLo = u >> 4, uu = u & 15;
        uint32_t dst = wbuf + isLo * W_HALF + r * AS + uu * 16;
        const __nv_bfloat16* src = (isLo ? g_w1l : g_w1h) + (size_t)(c * 64 + r) * DI + uu * 8;
        CP_ASYNC16(dst, src);
    }
}

__global__ __launch_bounds__(256, 1) void k_main(
    const float* __restrict__ x_items,
    const float* __restrict__ b1)
{
    extern __shared__ char sm[];
    const uint32_t sb = smem_u32(sm);
    const int tile = blockIdx.x;
    const int b    = blockIdx.y;
    const int tid  = threadIdx.x;
    const int wid  = tid >> 5;
    const int lane = tid & 31;
    const int mw   = wid & 3;            // item group (16 items)
    const int nh   = wid >> 2;           // dim half (32 dims within 64-chunk)
    const int n0   = tile * TM;
    const int q    = lane >> 2, t4 = lane & 3;

    float* su  = (float*)(sm + OFF_U);
    float* sb1 = (float*)(sm + OFF_B1);
    float* sp  = (float*)(sm + OFF_SP);
    float* spr = (float*)(sm + OFF_PR);

    for (int j = tid; j < D_; j += 256) { su[j] = g_u[b * D_ + j]; sb1[j] = b1[j]; }

    // stage X tile -> A hi/lo bf16 rows (item-major, 272B stride)
    {
        const float4* xs = (const float4*)(x_items + ((size_t)b * N_ + n0) * DI);
        #pragma unroll
        for (int it = 0; it < 8; ++it) {
            int e = it * 256 + tid;        // 64 items x 32 quads
            int i = e >> 5, qd = e & 31;
            float4 v = xs[i * 32 + qd];
            __nv_bfloat16 h0 = __float2bfloat16(v.x), h1v = __float2bfloat16(v.y);
            __nv_bfloat16 h2v = __float2bfloat16(v.z), h3 = __float2bfloat16(v.w);
            __nv_bfloat16 l0 = __float2bfloat16(v.x - __bfloat162float(h0));
            __nv_bfloat16 l1 = __float2bfloat16(v.y - __bfloat162float(h1v));
            __nv_bfloat16 l2 = __float2bfloat16(v.z - __bfloat162float(h2v));
            __nv_bfloat16 l3 = __float2bfloat16(v.w - __bfloat162float(h3));
            __nv_bfloat162 hp0 = __nv_bfloat162(h0, h1v), hp1 = __nv_bfloat162(h2v, h3);
            __nv_bfloat162 lp0 = __nv_bfloat162(l0, l1),  lp1 = __nv_bfloat162(l2, l3);
            int off = i * AS + qd * 8;
            *(uint32_t*)(sm + OFF_A + off)              = *(uint32_t*)&hp0;
            *(uint32_t*)(sm + OFF_A + off + 4)          = *(uint32_t*)&hp1;
            *(uint32_t*)(sm + OFF_A + A_HALF + off)     = *(uint32_t*)&lp0;
            *(uint32_t*)(sm + OFF_A + A_HALF + off + 4) = *(uint32_t*)&lp1;
        }
    }
    load_w_async(0, sb + OFF_W, tid);
    CP_COMMIT();

    // precomputed ldmatrix lane addresses
    const uint32_t arow_hi = sb + OFF_A + (mw * 16 + (lane & 15)) * AS + (lane >> 4) * 16;
    const uint32_t arow_lo = arow_hi + A_HALF;
    const uint32_t brow_off = (nh * 32 + (lane & 7) + ((lane >> 4) & 1) * 8) * AS + ((lane >> 3) & 1) * 16;

    float s0 = 0.f, s1 = 0.f;     // score partials for rows mw*16+q and +8

    for (int c = 0; c < 8; ++c) {
        const int buf = c & 1;
        if (c < 7) {
            load_w_async(c + 1, sb + OFF_W + (buf ^ 1) * W_BUF, tid);
            CP_COMMIT();
            CP_WAIT1();
        } else {
            CP_WAIT0();
        }
        __syncthreads();

        float acc[4][4] = {};
        const uint32_t wb = sb + OFF_W + buf * W_BUF;
        const uint32_t brow_hi = wb + brow_off;
        const uint32_t brow_lo = brow_hi + W_HALF;
        #pragma unroll
        for (int ks = 0; ks < 8; ++ks) {
            uint32_t ah[4], al[4];
            ldsm4(ah, arow_hi + ks * 32);
            ldsm4(al, arow_lo + ks * 32);
            #pragma unroll
            for (int p = 0; p < 2; ++p) {
                uint32_t bh[4], bl[4];
                ldsm4(bh, brow_hi + p * 16 * AS + ks * 32);
                ldsm4(bl, brow_lo + p * 16 * AS + ks * 32);
                mma_bf16(acc[2*p],   ah, bh[0], bh[1]);
                mma_bf16(acc[2*p+1], ah, bh[2], bh[3]);
                mma_bf16(acc[2*p],   ah, bl[0], bl[1]);
                mma_bf16(acc[2*p+1], ah, bl[2], bl[3]);
                mma_bf16(acc[2*p],   al, bh[0], bh[1]);
                mma_bf16(acc[2*p+1], al, bh[2], bh[3]);
            }
        }

        // epilogue for this 64-dim chunk (fp16 H1; proven delta ~2e-6)
        const int jb = c * 64 + nh * 32;
        const int r0 = mw * 16 + q;
        char* h1p = sm + OFF_H1;
        #pragma unroll
        for (int nt = 0; nt < 4; ++nt) {
            int j0 = jb + nt * 8 + t4 * 2;
            float b0v = sb1[j0], b1v = sb1[j0 + 1];
            float u0 = su[j0], u1 = su[j0 + 1];
            float h00 = gelu_f(acc[nt][0] + b0v);
            float h01 = gelu_f(acc[nt][1] + b1v);
            float h10 = gelu_f(acc[nt][2] + b0v);
            float h11 = gelu_f(acc[nt][3] + b1v);
            s0 = fmaf(h00, u0, fmaf(h01, u1, s0));
            s1 = fmaf(h10, u0, fmaf(h11, u1, s1));
            *(__half2*)(h1p + r0 * H1S + j0 * 2)       = __floats2half2_rn(h00, h01);
            *(__half2*)(h1p + (r0 + 8) * H1S + j0 * 2) = __floats2half2_rn(h10, h11);
        }
        __syncthreads();
    }

    // score reduction: sum over t4 lanes
    s0 += __shfl_xor_sync(0xffffffffu, s0, 1);
    s0 += __shfl_xor_sync(0xffffffffu, s0, 2);
    s1 += __shfl_xor_sync(0xffffffffu, s1, 1);
    s1 += __shfl_xor_sync(0xffffffffu, s1, 2);
    if (t4 == 0) {
        sp[nh * 64 + mw * 16 + q]     = s0;
        sp[nh * 64 + mw * 16 + q + 8] = s1;
    }
    __syncthreads();

    // softmax over 64 items (warp 0)
    if (wid == 0) {
        const float cb = g_c[b];
        float v0 = (sp[lane] + sp[64 + lane] + cb) * 0.044194173824159216f;
        float v1 = (sp[32 + lane] + sp[96 + lane] + cb) * 0.044194173824159216f;
        float m = fmaxf(v0, v1);
        for (int o = 16; o; o >>= 1) m = fmaxf(m, __shfl_xor_sync(0xffffffffu, m, o));
        float p0 = expf(v0 - m), p1 = expf(v1 - m);
        float l = p0 + p1;
        for (int o = 16; o; o >>= 1) l += __shfl_xor_sync(0xffffffffu, l, o);
        spr[lane] = p0;
        spr[lane + 32] = p1;
        if (lane == 0) {
            g_pm[b * NT3 + tile] = m;
            g_pl[b * NT3 + tile] = l;
        }
    }
    __syncthreads();

    // pacc[dim] = sum_items p[i] * H1[i][dim]; thread handles dims 2*tid, +1
    {
        const char* h1p = sm + OFF_H1;
        float ax = 0.f, ay = 0.f;
        #pragma unroll 8
        for (int i = 0; i < TM; ++i) {
            float2 h = __half22float2(*(const __half2*)(h1p + i * H1S + tid * 4));
            float p = spr[i];
            ax = fmaf(p, h.x, ax);
            ay = fmaf(p, h.y, ay);
        }
        float2* dst = (float2*)(g_pacc + ((size_t)(b * NT3 + tile)) * D_) + tid;
        *dst = make_float2(ax, ay);
    }
}

// =========================================================================
// k_final: combine tile partials, folded V proj, phi MLP (trusted round-11).
// grid=B_, block=256
// =========================================================================
__global__ __launch_bounds__(256) void k_final(
    const float* __restrict__ pw1, const float* __restrict__ pb1,
    const float* __restrict__ pw2, const float* __restrict__ pb2,
    float* __restrict__ out)
{
    __shared__ float s_scale[NT3];
    __shared__ float s_zh[D_], s_z[D_], s_h[D_];
    __shared__ float s_red[8];
    __shared__ float s_M, s_L;

    const int b   = blockIdx.x;
    const int tid = threadIdx.x;
    const int lane = tid & 31, warp = tid >> 5;

    const float m = (tid < NT3) ? g_pm[b * NT3 + tid] : -3e38f;
    float mw = m;
    for (int o = 16; o; o >>= 1) mw = fmaxf(mw, __shfl_xor_sync(0xffffffffu, mw, o));
    if (lane == 0) s_red[warp] = mw;
    __syncthreads();
    if (tid == 0) {
        float t = s_red[0];
        for (int i = 1; i < 8; i++) t = fmaxf(t, s_red[i]);
        s_M = t;
    }
    __syncthreads();
    const float M = s_M;
    const float sc = expf(m - M);
    if (tid < NT3) s_scale[tid] = sc;
    float lp = (tid < NT3) ? g_pl[b * NT3 + tid] * sc : 0.f;
    for (int o = 16; o; o >>= 1) lp += __shfl_xor_sync(0xffffffffu, lp, o);
    __syncthreads();
    if (lane == 0) s_red[warp] = lp;
    __syncthreads();
    if (tid == 0) {
        float t = 0.f;
        for (int i = 0; i < 8; i++) t += s_red[i];
        s_L = t;
    }
    __syncthreads();
    const float invL = 1.0f / s_L;

    for (int j = tid; j < D_; j += 256) {
        const float* base = g_pacc + ((size_t)b * NT3) * D_ + j;
        float s = 0.f;
        #pragma unroll 8
        for (int i = 0; i < NT3; i++) s = fmaf(base[(size_t)i * D_], s_scale[i], s);
        s_zh[j] = s * invL;
    }
    __syncthreads();

    for (int j = tid; j < D_; j += 256) {
        const float4* wr = (const float4*)(g_M + (size_t)j * D_);
        float s = 0.f;
        #pragma unroll 8
        for (int i = 0; i < D_ / 4; i++) {
            float4 w = wr[i];
            s += w.x * s_zh[4*i] + w.y * s_zh[4*i+1] + w.z * s_zh[4*i+2] + w.w * s_zh[4*i+3];
        }
        s_z[j] = s + g_d[j];
    }
    __syncthreads();

    for (int j = tid; j < D_; j += 256) {
        const float4* wr = (const float4*)(pw1 + (size_t)j * D_);
        float s = 0.f;
        #pragma unroll 8
        for (int i = 0; i < D_ / 4; i++) {
            float4 w = wr[i];
            s += w.x * s_z[4*i] + w.y * s_z[4*i+1] + w.z * s_z[4*i+2] + w.w * s_z[4*i+3];
        }
        s_h[j] = gelu_f(s + pb1[j]);
    }
    __syncthreads();

    for (int c = tid; c < NC; c += 256) {
        const float4* wr = (const float4*)(pw2 + (size_t)c * D_);
        float s = 0.f;
        #pragma unroll 8
        for (int i = 0; i < D_ / 4; i++) {
            float4 w = wr[i];
            s += w.x * s_h[4*i] + w.y * s_h[4*i+1] + w.z * s_h[4*i+2] + w.w * s_h[4*i+3];
        }
        out[(size_t)b * NC + c] = s + pb2[c];
    }
}

// =========================================================================
extern "C" void kernel_launch(void* const* d_in, const int* in_sizes, int n_in,
                              void* d_out, int out_size)
{
    const float* x_items = (const float*)d_in[0];
    const float* x_query = (const float*)d_in[1];
    const float* pxw1    = (const float*)d_in[2];
    const float* pxb1    = (const float*)d_in[3];
    const float* pxw2    = (const float*)d_in[4];
    const float* pxb2    = (const float*)d_in[5];
    const float* pqw1    = (const float*)d_in[6];
    const float* pqb1    = (const float*)d_in[7];
    const float* pqw2    = (const float*)d_in[8];
    const float* pqb2    = (const float*)d_in[9];
    const float* qw      = (const float*)d_in[10];
    const float* qb      = (const float*)d_in[11];
    const float* kw      = (const float*)d_in[12];
    const float* kb      = (const float*)d_in[13];
    const float* vw      = (const float*)d_in[14];
    const float* vb      = (const float*)d_in[15];
    const float* pw1     = (const float*)d_in[16];
    const float* pb1     = (const float*)d_in[17];
    const float* pw2     = (const float*)d_in[18];
    const float* pb2     = (const float*)d_in[19];
    float* out = (float*)d_out;

    cudaFuncSetAttribute(k_main, cudaFuncAttributeMaxDynamicSharedMemorySize, SMEM_MAIN);

    k_conv<<<256, 256>>>(pxw1);
    k_prep<<<128, 256>>>(kw, pxw2, pxb2, vw, vb);
    k_query<<<B_, D_>>>(x_query, pqw1, pqb1, pqw2, pqb2, qw, qb, kb);
    k_main<<<dim3(NT3, B_), 256, SMEM_MAIN>>>(x_items, pxb1);
    k_final<<<B_, 256>>>(pw1, pb1, pw2, pb2, out);
}

// round 15
// speedup vs baseline: 7.8139x; 1.1040x over previous
#include <cuda_runtime.h>
#include <cuda_bf16.h>
#include <cuda_fp16.h>
#include <math.h>
#include <stddef.h>
#include <stdint.h>

#define B_  32
#define N_  8192
#define DI  128
#define D_  512
#define NC  1000
#define TM  64            // items per tile
#define NT3 128           // tiles per batch

// ---------------- device scratch (static allocation only) ----------------
__device__ float g_P[D_ * D_];           // kw @ w2   (score fold)
__device__ float g_e[D_];                // kw @ b2
__device__ float g_M[D_ * D_];           // vw @ w2   (value fold)
__device__ float g_d[D_];                // vw @ b2 + vb
__device__ float g_u[B_ * D_];           // per-batch score vector (H1 space)
__device__ float g_c[B_];                // per-batch score constant
__device__ float g_pm[B_ * NT3];         // per-tile softmax max
__device__ float g_pl[B_ * NT3];         // per-tile softmax sum
__device__ float g_pacc[B_ * NT3 * D_];  // per-tile weighted H1 accum (8.4 MB)
__device__ __align__(16) __half g_h1[(size_t)B_ * N_ * D_];  // H1 scratch (268 MB, L2-resident per wave)
__device__ __align__(16) __nv_bfloat16 g_w1h[D_ * DI];  // W1 split hi
__device__ __align__(16) __nv_bfloat16 g_w1l[D_ * DI];  // W1 split lo

__device__ __forceinline__ float gelu_f(float x) {
    return 0.5f * x * (1.0f + erff(x * 0.70710678118654752440f));
}
__device__ __forceinline__ uint32_t smem_u32(const void* p) {
    uint32_t a;
    asm("{ .reg .u64 t; cvta.to.shared.u64 t, %1; cvt.u32.u64 %0, t; }" : "=r"(a) : "l"(p));
    return a;
}
__device__ __forceinline__ void ldsm4(uint32_t* r, uint32_t addr) {
    asm volatile("ldmatrix.sync.aligned.m8n8.x4.shared.b16 {%0,%1,%2,%3}, [%4];"
        : "=r"(r[0]), "=r"(r[1]), "=r"(r[2]), "=r"(r[3]) : "r"(addr));
}
__device__ __forceinline__ void mma_bf16(float* c, const uint32_t* a, uint32_t b0, uint32_t b1) {
    asm volatile("mma.sync.aligned.m16n8k16.row.col.f32.bf16.bf16.f32 "
        "{%0,%1,%2,%3}, {%4,%5,%6,%7}, {%8,%9}, {%0,%1,%2,%3};"
        : "+f"(c[0]), "+f"(c[1]), "+f"(c[2]), "+f"(c[3])
        : "r"(a[0]), "r"(a[1]), "r"(a[2]), "r"(a[3]), "r"(b0), "r"(b1));
}
#define CP_ASYNC16(dst, src) asm volatile("cp.async.cg.shared.global [%0], [%1], 16;" :: "r"(dst), "l"(src) : "memory")
#define CP_COMMIT()          asm volatile("cp.async.commit_group;" ::: "memory")
#define CP_WAIT1()           asm volatile("cp.async.wait_group 1;" ::: "memory")
#define CP_WAIT0()           asm volatile("cp.async.wait_group 0;" ::: "memory")

// ---------------- k_main SMEM layout (bytes) ----------------
// A rows (items): 256B data + 16B pad = 272B stride -> conflict-free ldmatrix
#define AS 272
#define A_HALF (TM * AS)              // 17408 (hi or lo)
#define OFF_A   0                      // hi, then lo
#define W_HALF (64 * AS)               // 17408 per chunk half
#define W_BUF  (2 * W_HALF)            // 34816: hi + lo
#define OFF_W  (2 * A_HALF)            // 34816; two buffers -> 104448
#define OFF_U  (OFF_W + 2 * W_BUF)     // 104448; 512 floats
#define OFF_B1 (OFF_U + 2048)          // 106496; 512 floats
#define OFF_SP (OFF_B1 + 2048)         // 108544; 2*64 floats
#define OFF_PR (OFF_SP + 512)          // 109056; 64 floats
#define SMEM_MAIN (OFF_PR + 256 + 64)  // 109376 -> 2 CTAs/SM

// =========================================================================
// k_conv: split W1 into bf16 hi/lo. grid=256, block=256
// =========================================================================
__global__ __launch_bounds__(256) void k_conv(const float* __restrict__ w1) {
    int i = blockIdx.x * 256 + threadIdx.x;
    float v = w1[i];
    __nv_bfloat16 h = __float2bfloat16(v);
    g_w1h[i] = h;
    g_w1l[i] = __float2bfloat16(v - __bfloat162float(h));
}

// =========================================================================
// k_prep: folded weight products (trusted). grid=128, block=256
// =========================================================================
__global__ __launch_bounds__(256) void k_prep(
    const float* __restrict__ kw, const float* __restrict__ w2,
    const float* __restrict__ b2, const float* __restrict__ vw,
    const float* __restrict__ vb)
{
    __shared__ float sA[8][D_];
    const int blk = blockIdx.x;
    const bool isM = blk >= 64;
    const int r0 = (blk & 63) * 8;
    const float* A = isM ? vw : kw;
    const int tid = threadIdx.x;

    for (int e = tid; e < 8 * (D_ / 4); e += 256) {
        int r = e / (D_ / 4), c = e % (D_ / 4);
        ((float4*)sA[r])[c] = ((const float4*)(A + (size_t)(r0 + r) * D_))[c];
    }
    __syncthreads();

    float* OUT = isM ? g_M : g_P;
    for (int j = tid; j < D_; j += 256) {
        float acc[8] = {};
        #pragma unroll 4
        for (int k = 0; k < D_; k++) {
            float wv = w2[(size_t)k * D_ + j];
            #pragma unroll
            for (int r = 0; r < 8; r++) acc[r] = fmaf(sA[r][k], wv, acc[r]);
        }
        #pragma unroll
        for (int r = 0; r < 8; r++) OUT[(size_t)(r0 + r) * D_ + j] = acc[r];
    }
    if (tid < 8) {
        float s = 0.f;
        #pragma unroll 8
        for (int k = 0; k < D_; k++) s = fmaf(sA[tid][k], b2[k], s);
        if (isM) g_d[r0 + tid] = s + vb[r0 + tid];
        else     g_e[r0 + tid] = s;
    }
}

// =========================================================================
// k_query: monolithic query path (trusted). grid=B_, block=512
// =========================================================================
__global__ __launch_bounds__(512) void k_query(
    const float* __restrict__ x_query,
    const float* __restrict__ w1, const float* __restrict__ b1,
    const float* __restrict__ w2, const float* __restrict__ b2,
    const float* __restrict__ qw, const float* __restrict__ qb,
    const float* __restrict__ kb)
{
    __shared__ float h1[D_], h2[D_], qv[D_];
    __shared__ float red[16];
    const int b = blockIdx.x;
    const int j = threadIdx.x;

    const float xq = x_query[b];
    h1[j] = gelu_f(fmaf(xq, w1[j], b1[j]));
    __syncthreads();

    {
        const float4* wr = (const float4*)(w2 + (size_t)j * D_);
        float s = 0.f;
        #pragma unroll 8
        for (int i = 0; i < D_ / 4; i++) {
            float4 w = wr[i];
            s += w.x * h1[4*i] + w.y * h1[4*i+1] + w.z * h1[4*i+2] + w.w * h1[4*i+3];
        }
        h2[j] = s + b2[j];
    }
    __syncthreads();
    {
        const float4* wr = (const float4*)(qw + (size_t)j * D_);
        float s = 0.f;
        #pragma unroll 8
        for (int i = 0; i < D_ / 4; i++) {
            float4 w = wr[i];
            s += w.x * h2[4*i] + w.y * h2[4*i+1] + w.z * h2[4*i+2] + w.w * h2[4*i+3];
        }
        qv[j] = s + qb[j];
    }
    __syncthreads();

    {
        float s = 0.f;
        #pragma unroll 8
        for (int m = 0; m < D_; m++) s = fmaf(qv[m], g_P[(size_t)m * D_ + j], s);
        g_u[b * D_ + j] = s;
    }
    {
        float p = qv[j] * (g_e[j] + kb[j]);
        for (int o = 16; o; o >>= 1) p += __shfl_down_sync(0xffffffffu, p, o);
        if ((j & 31) == 0) red[j >> 5] = p;
        __syncthreads();
        if (j == 0) {
            float t = 0.f;
            for (int i = 0; i < 16; i++) t += red[i];
            g_c[b] = t;
        }
    }
}

// =========================================================================
// k_main: split-bf16 HMMA GEMM1 (ldmatrix + cp.async) + gelu + scores +
// softmax partials. H1 -> global scratch (L2-resident). 2 CTAs/SM.
// grid=(NT3, B_), block=256 (8 warps)
// =========================================================================
__device__ __forceinline__ void load_w_async(int c, uint32_t wbuf, int tid) {
    #pragma unroll
    for (int it = 0; it < 8; ++it) {
        int e = it * 256 + tid;          // 0..2047
        int r = e >> 5, u = e & 31;
        int isLo = u >> 4, uu = u & 15;
        uint32_t dst = wbuf + isLo * W_HALF + r * AS + uu * 16;
        const __nv_bfloat16* src = (isLo ? g_w1l : g_w1h) + (size_t)(c * 64 + r) * DI + uu * 8;
        CP_ASYNC16(dst, src);
    }
}

__global__ __launch_bounds__(256, 2) void k_main(
    const float* __restrict__ x_items,
    const float* __restrict__ b1)
{
    extern __shared__ char sm[];
    const uint32_t sb = smem_u32(sm);
    const int tile = blockIdx.x;
    const int b    = blockIdx.y;
    const int tid  = threadIdx.x;
    const int wid  = tid >> 5;
    const int lane = tid & 31;
    const int mw   = wid & 3;            // item group (16 items)
    const int nh   = wid >> 2;           // dim half (32 dims within 64-chunk)
    const int n0   = tile * TM;
    const int q    = lane >> 2, t4 = lane & 3;

    float* su  = (float*)(sm + OFF_U);
    float* sb1 = (float*)(sm + OFF_B1);
    float* sp  = (float*)(sm + OFF_SP);
    float* spr = (float*)(sm + OFF_PR);

    // per-tile H1 scratch (half2 view): index = item*256 + (dim>>1)
    __half2* h1g = (__half2*)(g_h1 + ((size_t)(b * NT3 + tile) * TM) * D_);

    for (int j = tid; j < D_; j += 256) { su[j] = g_u[b * D_ + j]; sb1[j] = b1[j]; }

    // stage X tile -> A hi/lo bf16 rows (item-major, 272B stride)
    {
        const float4* xs = (const float4*)(x_items + ((size_t)b * N_ + n0) * DI);
        #pragma unroll
        for (int it = 0; it < 8; ++it) {
            int e = it * 256 + tid;        // 64 items x 32 quads
            int i = e >> 5, qd = e & 31;
            float4 v = xs[i * 32 + qd];
            __nv_bfloat16 h0 = __float2bfloat16(v.x), h1v = __float2bfloat16(v.y);
            __nv_bfloat16 h2v = __float2bfloat16(v.z), h3 = __float2bfloat16(v.w);
            __nv_bfloat16 l0 = __float2bfloat16(v.x - __bfloat162float(h0));
            __nv_bfloat16 l1 = __float2bfloat16(v.y - __bfloat162float(h1v));
            __nv_bfloat16 l2 = __float2bfloat16(v.z - __bfloat162float(h2v));
            __nv_bfloat16 l3 = __float2bfloat16(v.w - __bfloat162float(h3));
            __nv_bfloat162 hp0 = __nv_bfloat162(h0, h1v), hp1 = __nv_bfloat162(h2v, h3);
            __nv_bfloat162 lp0 = __nv_bfloat162(l0, l1),  lp1 = __nv_bfloat162(l2, l3);
            int off = i * AS + qd * 8;
            *(uint32_t*)(sm + OFF_A + off)              = *(uint32_t*)&hp0;
            *(uint32_t*)(sm + OFF_A + off + 4)          = *(uint32_t*)&hp1;
            *(uint32_t*)(sm + OFF_A + A_HALF + off)     = *(uint32_t*)&lp0;
            *(uint32_t*)(sm + OFF_A + A_HALF + off + 4) = *(uint32_t*)&lp1;
        }
    }
    load_w_async(0, sb + OFF_W, tid);
    CP_COMMIT();

    // precomputed ldmatrix lane addresses
    const uint32_t arow_hi = sb + OFF_A + (mw * 16 + (lane & 15)) * AS + (lane >> 4) * 16;
    const uint32_t arow_lo = arow_hi + A_HALF;
    const uint32_t brow_off = (nh * 32 + (lane & 7) + ((lane >> 4) & 1) * 8) * AS + ((lane >> 3) & 1) * 16;

    float s0 = 0.f, s1 = 0.f;     // score partials for rows mw*16+q and +8

    for (int c = 0; c < 8; ++c) {
        const int buf = c & 1;
        if (c < 7) {
            load_w_async(c + 1, sb + OFF_W + (buf ^ 1) * W_BUF, tid);
            CP_COMMIT();
            CP_WAIT1();
        } else {
            CP_WAIT0();
        }
        __syncthreads();

        float acc[4][4] = {};
        const uint32_t wb = sb + OFF_W + buf * W_BUF;
        const uint32_t brow_hi = wb + brow_off;
        const uint32_t brow_lo = brow_hi + W_HALF;
        #pragma unroll
        for (int ks = 0; ks < 8; ++ks) {
            uint32_t ah[4], al[4];
            ldsm4(ah, arow_hi + ks * 32);
            ldsm4(al, arow_lo + ks * 32);
            #pragma unroll
            for (int p = 0; p < 2; ++p) {
                uint32_t bh[4], bl[4];
                ldsm4(bh, brow_hi + p * 16 * AS + ks * 32);
                ldsm4(bl, brow_lo + p * 16 * AS + ks * 32);
                mma_bf16(acc[2*p],   ah, bh[0], bh[1]);
                mma_bf16(acc[2*p+1], ah, bh[2], bh[3]);
                mma_bf16(acc[2*p],   ah, bl[0], bl[1]);
                mma_bf16(acc[2*p+1], ah, bl[2], bl[3]);
                mma_bf16(acc[2*p],   al, bh[0], bh[1]);
                mma_bf16(acc[2*p+1], al, bh[2], bh[3]);
            }
        }

        // epilogue for this 64-dim chunk: gelu + score dot + H1 -> global
        const int jb = c * 64 + nh * 32;
        const int r0 = mw * 16 + q;
        #pragma unroll
        for (int nt = 0; nt < 4; ++nt) {
            int j0 = jb + nt * 8 + t4 * 2;
            float b0v = sb1[j0], b1v = sb1[j0 + 1];
            float u0 = su[j0], u1 = su[j0 + 1];
            float h00 = gelu_f(acc[nt][0] + b0v);
            float h01 = gelu_f(acc[nt][1] + b1v);
            float h10 = gelu_f(acc[nt][2] + b0v);
            float h11 = gelu_f(acc[nt][3] + b1v);
            s0 = fmaf(h00, u0, fmaf(h01, u1, s0));
            s1 = fmaf(h10, u0, fmaf(h11, u1, s1));
            h1g[r0 * 256 + (j0 >> 1)]       = __floats2half2_rn(h00, h01);
            h1g[(r0 + 8) * 256 + (j0 >> 1)] = __floats2half2_rn(h10, h11);
        }
        __syncthreads();
    }

    // score reduction: sum over t4 lanes
    s0 += __shfl_xor_sync(0xffffffffu, s0, 1);
    s0 += __shfl_xor_sync(0xffffffffu, s0, 2);
    s1 += __shfl_xor_sync(0xffffffffu, s1, 1);
    s1 += __shfl_xor_sync(0xffffffffu, s1, 2);
    if (t4 == 0) {
        sp[nh * 64 + mw * 16 + q]     = s0;
        sp[nh * 64 + mw * 16 + q + 8] = s1;
    }
    __syncthreads();

    // softmax over 64 items (warp 0)
    if (wid == 0) {
        const float cb = g_c[b];
        float v0 = (sp[lane] + sp[64 + lane] + cb) * 0.044194173824159216f;
        float v1 = (sp[32 + lane] + sp[96 + lane] + cb) * 0.044194173824159216f;
        float m = fmaxf(v0, v1);
        for (int o = 16; o; o >>= 1) m = fmaxf(m, __shfl_xor_sync(0xffffffffu, m, o));
        float p0 = expf(v0 - m), p1 = expf(v1 - m);
        float l = p0 + p1;
        for (int o = 16; o; o >>= 1) l += __shfl_xor_sync(0xffffffffu, l, o);
        spr[lane] = p0;
        spr[lane + 32] = p1;
        if (lane == 0) {
            g_pm[b * NT3 + tile] = m;
            g_pl[b * NT3 + tile] = l;
        }
    }
    __syncthreads();

    // pacc[dim] = sum_items p[i] * H1[i][dim]; thread handles dims 2*tid, +1
    // (reads tile H1 back from global -- L2-resident)
    {
        float ax = 0.f, ay = 0.f;
        const __half2* h1c = h1g + tid;
        #pragma unroll 8
        for (int i = 0; i < TM; ++i) {
            float2 h = __half22float2(h1c[i * 256]);
            float p = spr[i];
            ax = fmaf(p, h.x, ax);
            ay = fmaf(p, h.y, ay);
        }
        float2* dst = (float2*)(g_pacc + ((size_t)(b * NT3 + tile)) * D_) + tid;
        *dst = make_float2(ax, ay);
    }
}

// =========================================================================
// k_final: combine tile partials, folded V proj, phi MLP (trusted).
// grid=B_, block=256
// =========================================================================
__global__ __launch_bounds__(256) void k_final(
    const float* __restrict__ pw1, const float* __restrict__ pb1,
    const float* __restrict__ pw2, const float* __restrict__ pb2,
    float* __restrict__ out)
{
    __shared__ float s_scale[NT3];
    __shared__ float s_zh[D_], s_z[D_], s_h[D_];
    __shared__ float s_red[8];
    __shared__ float s_M, s_L;

    const int b   = blockIdx.x;
    const int tid = threadIdx.x;
    const int lane = tid & 31, warp = tid >> 5;

    const float m = (tid < NT3) ? g_pm[b * NT3 + tid] : -3e38f;
    float mw = m;
    for (int o = 16; o; o >>= 1) mw = fmaxf(mw, __shfl_xor_sync(0xffffffffu, mw, o));
    if (lane == 0) s_red[warp] = mw;
    __syncthreads();
    if (tid == 0) {
        float t = s_red[0];
        for (int i = 1; i < 8; i++) t = fmaxf(t, s_red[i]);
        s_M = t;
    }
    __syncthreads();
    const float M = s_M;
    const float sc = expf(m - M);
    if (tid < NT3) s_scale[tid] = sc;
    float lp = (tid < NT3) ? g_pl[b * NT3 + tid] * sc : 0.f;
    for (int o = 16; o; o >>= 1) lp += __shfl_xor_sync(0xffffffffu, lp, o);
    __syncthreads();
    if (lane == 0) s_red[warp] = lp;
    __syncthreads();
    if (tid == 0) {
        float t = 0.f;
        for (int i = 0; i < 8; i++) t += s_red[i];
        s_L = t;
    }
    __syncthreads();
    const float invL = 1.0f / s_L;

    for (int j = tid; j < D_; j += 256) {
        const float* base = g_pacc + ((size_t)b * NT3) * D_ + j;
        float s = 0.f;
        #pragma unroll 8
        for (int i = 0; i < NT3; i++) s = fmaf(base[(size_t)i * D_], s_scale[i], s);
        s_zh[j] = s * invL;
    }
    __syncthreads();

    for (int j = tid; j < D_; j += 256) {
        const float4* wr = (const float4*)(g_M + (size_t)j * D_);
        float s = 0.f;
        #pragma unroll 8
        for (int i = 0; i < D_ / 4; i++) {
            float4 w = wr[i];
            s += w.x * s_zh[4*i] + w.y * s_zh[4*i+1] + w.z * s_zh[4*i+2] + w.w * s_zh[4*i+3];
        }
        s_z[j] = s + g_d[j];
    }
    __syncthreads();

    for (int j = tid; j < D_; j += 256) {
        const float4* wr = (const float4*)(pw1 + (size_t)j * D_);
        float s = 0.f;
        #pragma unroll 8
        for (int i = 0; i < D_ / 4; i++) {
            float4 w = wr[i];
            s += w.x * s_z[4*i] + w.y * s_z[4*i+1] + w.z * s_z[4*i+2] + w.w * s_z[4*i+3];
        }
        s_h[j] = gelu_f(s + pb1[j]);
    }
    __syncthreads();

    for (int c = tid; c < NC; c += 256) {
        const float4* wr = (const float4*)(pw2 + (size_t)c * D_);
        float s = 0.f;
        #pragma unroll 8
        for (int i = 0; i < D_ / 4; i++) {
            float4 w = wr[i];
            s += w.x * s_h[4*i] + w.y * s_h[4*i+1] + w.z * s_h[4*i+2] + w.w * s_h[4*i+3];
        }
        out[(size_t)b * NC + c] = s + pb2[c];
    }
}

// =========================================================================
extern "C" void kernel_launch(void* const* d_in, const int* in_sizes, int n_in,
                              void* d_out, int out_size)
{
    const float* x_items = (const float*)d_in[0];
    const float* x_query = (const float*)d_in[1];
    const float* pxw1    = (const float*)d_in[2];
    const float* pxb1    = (const float*)d_in[3];
    const float* pxw2    = (const float*)d_in[4];
    const float* pxb2    = (const float*)d_in[5];
    const float* pqw1    = (const float*)d_in[6];
    const float* pqb1    = (const float*)d_in[7];
    const float* pqw2    = (const float*)d_in[8];
    const float* pqb2    = (const float*)d_in[9];
    const float* qw      = (const float*)d_in[10];
    const float* qb      = (const float*)d_in[11];
    const float* kw      = (const float*)d_in[12];
    const float* kb      = (const float*)d_in[13];
    const float* vw      = (const float*)d_in[14];
    const float* vb      = (const float*)d_in[15];
    const float* pw1     = (const float*)d_in[16];
    const float* pb1     = (const float*)d_in[17];
    const float* pw2     = (const float*)d_in[18];
    const float* pb2     = (const float*)d_in[19];
    float* out = (float*)d_out;

    cudaFuncSetAttribute(k_main, cudaFuncAttributeMaxDynamicSharedMemorySize, SMEM_MAIN);

    k_conv<<<256, 256>>>(pxw1);
    k_prep<<<128, 256>>>(kw, pxw2, pxb2, vw, vb);
    k_query<<<B_, D_>>>(x_query, pqw1, pqb1, pqw2, pqb2, qw, qb, kb);
    k_main<<<dim3(NT3, B_), 256, SMEM_MAIN>>>(x_items, pxb1);
    k_final<<<B_, 256>>>(pw1, pb1, pw2, pb2, out);
}

// round 16
// speedup vs baseline: 8.7181x; 1.1157x over previous
#include <cuda_runtime.h>
#include <cuda_bf16.h>
#include <cuda_fp16.h>
#include <math.h>
#include <stddef.h>
#include <stdint.h>

#define B_  32
#define N_  8192
#define DI  128
#define D_  512
#define NC  1000
#define TM  64            // items per tile
#define NT3 128           // tiles per batch

// ---------------- device scratch (static allocation only) ----------------
__device__ float g_P[D_ * D_];           // kw @ w2   (score fold)
__device__ float g_e[D_];                // kw @ b2
__device__ float g_M[D_ * D_];           // vw @ w2   (value fold)
__device__ float g_d[D_];                // vw @ b2 + vb
__device__ float g_u[B_ * D_];           // per-batch score vector (H1 space)
__device__ float g_c[B_];                // per-batch score constant
__device__ float g_pm[B_ * NT3];         // per-tile softmax max
__device__ float g_pl[B_ * NT3];         // per-tile softmax sum
__device__ float g_pacc[B_ * NT3 * D_];  // per-tile weighted H1 accum (8.4 MB)
__device__ __align__(16) __half g_h1[(size_t)B_ * N_ * D_];  // H1 scratch (L2-resident per wave)
__device__ __align__(16) __half g_w1f[D_ * DI];              // W1 fp16

__device__ __forceinline__ float gelu_f(float x) {
    return 0.5f * x * (1.0f + erff(x * 0.70710678118654752440f));
}
__device__ __forceinline__ uint32_t smem_u32(const void* p) {
    uint32_t a;
    asm("{ .reg .u64 t; cvta.to.shared.u64 t, %1; cvt.u32.u64 %0, t; }" : "=r"(a) : "l"(p));
    return a;
}
__device__ __forceinline__ void ldsm4(uint32_t* r, uint32_t addr) {
    asm volatile("ldmatrix.sync.aligned.m8n8.x4.shared.b16 {%0,%1,%2,%3}, [%4];"
        : "=r"(r[0]), "=r"(r[1]), "=r"(r[2]), "=r"(r[3]) : "r"(addr));
}
__device__ __forceinline__ void mma_f16(float* c, const uint32_t* a, uint32_t b0, uint32_t b1) {
    asm volatile("mma.sync.aligned.m16n8k16.row.col.f32.f16.f16.f32 "
        "{%0,%1,%2,%3}, {%4,%5,%6,%7}, {%8,%9}, {%0,%1,%2,%3};"
        : "+f"(c[0]), "+f"(c[1]), "+f"(c[2]), "+f"(c[3])
        : "r"(a[0]), "r"(a[1]), "r"(a[2]), "r"(a[3]), "r"(b0), "r"(b1));
}
#define CP_ASYNC16(dst, src) asm volatile("cp.async.cg.shared.global [%0], [%1], 16;" :: "r"(dst), "l"(src) : "memory")
#define CP_COMMIT()          asm volatile("cp.async.commit_group;" ::: "memory")
#define CP_WAIT1()           asm volatile("cp.async.wait_group 1;" ::: "memory")
#define CP_WAIT0()           asm volatile("cp.async.wait_group 0;" ::: "memory")

// ---------------- k_main SMEM layout (bytes) ----------------
// A rows (items): 256B data + 16B pad = 272B stride -> conflict-free ldmatrix
#define AS 272
#define A_HALF (TM * AS)              // 17408 (Xh or Xl)
#define OFF_A   0                      // hi, then lo -> 34816
#define W_CHUNK (64 * AS)              // 17408 (Wh only, one 64-dim chunk)
#define OFF_W  (2 * A_HALF)            // 34816; double buffer -> 69632
#define OFF_U  (OFF_W + 2 * W_CHUNK)   // 69632; 512 floats
#define OFF_B1 (OFF_U + 2048)          // 71680; 512 floats
#define OFF_SP (OFF_B1 + 2048)         // 73728; 2*64 floats
#define OFF_PR (OFF_SP + 512)          // 74240; 64 floats
#define SMEM_MAIN (OFF_PR + 256 + 64)  // 74560 -> 2 CTAs/SM (regs permitting)

// =========================================================================
// k_conv: W1 -> fp16. grid=256, block=256
// =========================================================================
__global__ __launch_bounds__(256) void k_conv(const float* __restrict__ w1) {
    int i = blockIdx.x * 256 + threadIdx.x;
    g_w1f[i] = __float2half_rn(w1[i]);
}

// =========================================================================
// k_prep: folded weight products (trusted). grid=128, block=256
// =========================================================================
__global__ __launch_bounds__(256) void k_prep(
    const float* __restrict__ kw, const float* __restrict__ w2,
    const float* __restrict__ b2, const float* __restrict__ vw,
    const float* __restrict__ vb)
{
    __shared__ float sA[8][D_];
    const int blk = blockIdx.x;
    const bool isM = blk >= 64;
    const int r0 = (blk & 63) * 8;
    const float* A = isM ? vw : kw;
    const int tid = threadIdx.x;

    for (int e = tid; e < 8 * (D_ / 4); e += 256) {
        int r = e / (D_ / 4), c = e % (D_ / 4);
        ((float4*)sA[r])[c] = ((const float4*)(A + (size_t)(r0 + r) * D_))[c];
    }
    __syncthreads();

    float* OUT = isM ? g_M : g_P;
    for (int j = tid; j < D_; j += 256) {
        float acc[8] = {};
        #pragma unroll 4
        for (int k = 0; k < D_; k++) {
            float wv = w2[(size_t)k * D_ + j];
            #pragma unroll
            for (int r = 0; r < 8; r++) acc[r] = fmaf(sA[r][k], wv, acc[r]);
        }
        #pragma unroll
        for (int r = 0; r < 8; r++) OUT[(size_t)(r0 + r) * D_ + j] = acc[r];
    }
    if (tid < 8) {
        float s = 0.f;
        #pragma unroll 8
        for (int k = 0; k < D_; k++) s = fmaf(sA[tid][k], b2[k], s);
        if (isM) g_d[r0 + tid] = s + vb[r0 + tid];
        else     g_e[r0 + tid] = s;
    }
}

// =========================================================================
// k_query: monolithic query path (trusted). grid=B_, block=512
// =========================================================================
__global__ __launch_bounds__(512) void k_query(
    const float* __restrict__ x_query,
    const float* __restrict__ w1, const float* __restrict__ b1,
    const float* __restrict__ w2, const float* __restrict__ b2,
    const float* __restrict__ qw, const float* __restrict__ qb,
    const float* __restrict__ kb)
{
    __shared__ float h1[D_], h2[D_], qv[D_];
    __shared__ float red[16];
    const int b = blockIdx.x;
    const int j = threadIdx.x;

    const float xq = x_query[b];
    h1[j] = gelu_f(fmaf(xq, w1[j], b1[j]));
    __syncthreads();

    {
        const float4* wr = (const float4*)(w2 + (size_t)j * D_);
        float s = 0.f;
        #pragma unroll 8
        for (int i = 0; i < D_ / 4; i++) {
            float4 w = wr[i];
            s += w.x * h1[4*i] + w.y * h1[4*i+1] + w.z * h1[4*i+2] + w.w * h1[4*i+3];
        }
        h2[j] = s + b2[j];
    }
    __syncthreads();
    {
        const float4* wr = (const float4*)(qw + (size_t)j * D_);
        float s = 0.f;
        #pragma unroll 8
        for (int i = 0; i < D_ / 4; i++) {
            float4 w = wr[i];
            s += w.x * h2[4*i] + w.y * h2[4*i+1] + w.z * h2[4*i+2] + w.w * h2[4*i+3];
        }
        qv[j] = s + qb[j];
    }
    __syncthreads();

    {
        float s = 0.f;
        #pragma unroll 8
        for (int m = 0; m < D_; m++) s = fmaf(qv[m], g_P[(size_t)m * D_ + j], s);
        g_u[b * D_ + j] = s;
    }
    {
        float p = qv[j] * (g_e[j] + kb[j]);
        for (int o = 16; o; o >>= 1) p += __shfl_down_sync(0xffffffffu, p, o);
        if ((j & 31) == 0) red[j >> 5] = p;
        __syncthreads();
        if (j == 0) {
            float t = 0.f;
            for (int i = 0; i < 16; i++) t += red[i];
            g_c[b] = t;
        }
    }
}

// =========================================================================
// k_main: fp16 2-term HMMA GEMM1 (X split hi/lo, W single) + gelu + scores +
// softmax partials. H1 -> global scratch. grid=(NT3, B_), block=256
// =========================================================================
__device__ __forceinline__ void load_w_async(int c, uint32_t wbuf, int tid) {
    // chunk c: 64 dims x 128 k fp16 = 16KB data; 64 rows x 16 segs of 16B
    #pragma unroll
    for (int it = 0; it < 4; ++it) {
        int e = it * 256 + tid;          // 0..1023
        int r = e >> 4, seg = e & 15;
        uint32_t dst = wbuf + r * AS + seg * 16;
        const __half* src = g_w1f + (size_t)(c * 64 + r) * DI + seg * 8;
        CP_ASYNC16(dst, src);
    }
}

__global__ __launch_bounds__(256, 2) void k_main(
    const float* __restrict__ x_items,
    const float* __restrict__ b1)
{
    extern __shared__ char sm[];
    const uint32_t sb = smem_u32(sm);
    const int tile = blockIdx.x;
    const int b    = blockIdx.y;
    const int tid  = threadIdx.x;
    const int wid  = tid >> 5;
    const int lane = tid & 31;
    const int mw   = wid & 3;            // item group (16 items)
    const int nh   = wid >> 2;           // dim half (32 dims within 64-chunk)
    const int n0   = tile * TM;
    const int q    = lane >> 2, t4 = lane & 3;

    float* su  = (float*)(sm + OFF_U);
    float* sb1 = (float*)(sm + OFF_B1);
    float* sp  = (float*)(sm + OFF_SP);
    float* spr = (float*)(sm + OFF_PR);

    // per-tile H1 scratch (half2 view): index = item*256 + (dim>>1)
    __half2* h1g = (__half2*)(g_h1 + ((size_t)(b * NT3 + tile) * TM) * D_);

    for (int j = tid; j < D_; j += 256) { su[j] = g_u[b * D_ + j]; sb1[j] = b1[j]; }

    // stage X tile -> Xh/Xl fp16 rows (item-major, 272B stride)
    {
        const float4* xs = (const float4*)(x_items + ((size_t)b * N_ + n0) * DI);
        #pragma unroll
        for (int it = 0; it < 8; ++it) {
            int e = it * 256 + tid;        // 64 items x 32 quads
            int i = e >> 5, qd = e & 31;
            float4 v = xs[i * 32 + qd];
            __half h0 = __float2half_rn(v.x), h1v = __float2half_rn(v.y);
            __half h2v = __float2half_rn(v.z), h3 = __float2half_rn(v.w);
            __half l0 = __float2half_rn(v.x - __half2float(h0));
            __half l1 = __float2half_rn(v.y - __half2float(h1v));
            __half l2 = __float2half_rn(v.z - __half2float(h2v));
            __half l3 = __float2half_rn(v.w - __half2float(h3));
            __half2 hp0 = __halves2half2(h0, h1v), hp1 = __halves2half2(h2v, h3);
            __half2 lp0 = __halves2half2(l0, l1),  lp1 = __halves2half2(l2, l3);
            int off = i * AS + qd * 8;
            *(uint32_t*)(sm + OFF_A + off)              = *(uint32_t*)&hp0;
            *(uint32_t*)(sm + OFF_A + off + 4)          = *(uint32_t*)&hp1;
            *(uint32_t*)(sm + OFF_A + A_HALF + off)     = *(uint32_t*)&lp0;
            *(uint32_t*)(sm + OFF_A + A_HALF + off + 4) = *(uint32_t*)&lp1;
        }
    }
    load_w_async(0, sb + OFF_W, tid);
    CP_COMMIT();

    // precomputed ldmatrix lane addresses
    const uint32_t arow_hi = sb + OFF_A + (mw * 16 + (lane & 15)) * AS + (lane >> 4) * 16;
    const uint32_t arow_lo = arow_hi + A_HALF;
    const uint32_t brow_off = (nh * 32 + (lane & 7) + ((lane >> 4) & 1) * 8) * AS + ((lane >> 3) & 1) * 16;

    float s0 = 0.f, s1 = 0.f;     // score partials for rows mw*16+q and +8

    for (int c = 0; c < 8; ++c) {
        const int buf = c & 1;
        if (c < 7) {
            load_w_async(c + 1, sb + OFF_W + (buf ^ 1) * W_CHUNK, tid);
            CP_COMMIT();
            CP_WAIT1();
        } else {
            CP_WAIT0();
        }
        __syncthreads();

        float acc[4][4] = {};
        const uint32_t brow_hi = sb + OFF_W + buf * W_CHUNK + brow_off;
        #pragma unroll
        for (int ks = 0; ks < 8; ++ks) {
            uint32_t ah[4], al[4];
            ldsm4(ah, arow_hi + ks * 32);
            ldsm4(al, arow_lo + ks * 32);
            #pragma unroll
            for (int p = 0; p < 2; ++p) {
                uint32_t bh[4];
                ldsm4(bh, brow_hi + p * 16 * AS + ks * 32);
                mma_f16(acc[2*p],   ah, bh[0], bh[1]);
                mma_f16(acc[2*p+1], ah, bh[2], bh[3]);
                mma_f16(acc[2*p],   al, bh[0], bh[1]);
                mma_f16(acc[2*p+1], al, bh[2], bh[3]);
            }
        }
        __syncthreads();

        // epilogue for this 64-dim chunk: gelu + score dot + H1 -> global
        const int jb = c * 64 + nh * 32;
        const int r0 = mw * 16 + q;
        #pragma unroll
        for (int nt = 0; nt < 4; ++nt) {
            int j0 = jb + nt * 8 + t4 * 2;
            float b0v = sb1[j0], b1v = sb1[j0 + 1];
            float u0 = su[j0], u1 = su[j0 + 1];
            float h00 = gelu_f(acc[nt][0] + b0v);
            float h01 = gelu_f(acc[nt][1] + b1v);
            float h10 = gelu_f(acc[nt][2] + b0v);
            float h11 = gelu_f(acc[nt][3] + b1v);
            s0 = fmaf(h00, u0, fmaf(h01, u1, s0));
            s1 = fmaf(h10, u0, fmaf(h11, u1, s1));
            h1g[r0 * 256 + (j0 >> 1)]       = __floats2half2_rn(h00, h01);
            h1g[(r0 + 8) * 256 + (j0 >> 1)] = __floats2half2_rn(h10, h11);
        }
    }

    // score reduction: sum over t4 lanes
    s0 += __shfl_xor_sync(0xffffffffu, s0, 1);
    s0 += __shfl_xor_sync(0xffffffffu, s0, 2);
    s1 += __shfl_xor_sync(0xffffffffu, s1, 1);
    s1 += __shfl_xor_sync(0xffffffffu, s1, 2);
    if (t4 == 0) {
        sp[nh * 64 + mw * 16 + q]     = s0;
        sp[nh * 64 + mw * 16 + q + 8] = s1;
    }
    __syncthreads();

    // softmax over 64 items (warp 0)
    if (wid == 0) {
        const float cb = g_c[b];
        float v0 = (sp[lane] + sp[64 + lane] + cb) * 0.044194173824159216f;
        float v1 = (sp[32 + lane] + sp[96 + lane] + cb) * 0.044194173824159216f;
        float m = fmaxf(v0, v1);
        for (int o = 16; o; o >>= 1) m = fmaxf(m, __shfl_xor_sync(0xffffffffu, m, o));
        float p0 = expf(v0 - m), p1 = expf(v1 - m);
        float l = p0 + p1;
        for (int o = 16; o; o >>= 1) l += __shfl_xor_sync(0xffffffffu, l, o);
        spr[lane] = p0;
        spr[lane + 32] = p1;
        if (lane == 0) {
            g_pm[b * NT3 + tile] = m;
            g_pl[b * NT3 + tile] = l;
        }
    }
    __syncthreads();

    // pacc[dim] = sum_items p[i] * H1[i][dim]; thread handles dims 2*tid, +1
    {
        float ax = 0.f, ay = 0.f;
        const __half2* h1c = h1g + tid;
        #pragma unroll 8
        for (int i = 0; i < TM; ++i) {
            float2 h = __half22float2(h1c[i * 256]);
            float p = spr[i];
            ax = fmaf(p, h.x, ax);
            ay = fmaf(p, h.y, ay);
        }
        float2* dst = (float2*)(g_pacc + ((size_t)(b * NT3 + tile)) * D_) + tid;
        *dst = make_float2(ax, ay);
    }
}

// =========================================================================
// k_final: combine tile partials, folded V proj, phi MLP (trusted).
// grid=B_, block=256
// =========================================================================
__global__ __launch_bounds__(256) void k_final(
    const float* __restrict__ pw1, const float* __restrict__ pb1,
    const float* __restrict__ pw2, const float* __restrict__ pb2,
    float* __restrict__ out)
{
    __shared__ float s_scale[NT3];
    __shared__ float s_zh[D_], s_z[D_], s_h[D_];
    __shared__ float s_red[8];
    __shared__ float s_M, s_L;

    const int b   = blockIdx.x;
    const int tid = threadIdx.x;
    const int lane = tid & 31, warp = tid >> 5;

    const float m = (tid < NT3) ? g_pm[b * NT3 + tid] : -3e38f;
    float mw = m;
    for (int o = 16; o; o >>= 1) mw = fmaxf(mw, __shfl_xor_sync(0xffffffffu, mw, o));
    if (lane == 0) s_red[warp] = mw;
    __syncthreads();
    if (tid == 0) {
        float t = s_red[0];
        for (int i = 1; i < 8; i++) t = fmaxf(t, s_red[i]);
        s_M = t;
    }
    __syncthreads();
    const float M = s_M;
    const float sc = expf(m - M);
    if (tid < NT3) s_scale[tid] = sc;
    float lp = (tid < NT3) ? g_pl[b * NT3 + tid] * sc : 0.f;
    for (int o = 16; o; o >>= 1) lp += __shfl_xor_sync(0xffffffffu, lp, o);
    __syncthreads();
    if (lane == 0) s_red[warp] = lp;
    __syncthreads();
    if (tid == 0) {
        float t = 0.f;
        for (int i = 0; i < 8; i++) t += s_red[i];
        s_L = t;
    }
    __syncthreads();
    const float invL = 1.0f / s_L;

    for (int j = tid; j < D_; j += 256) {
        const float* base = g_pacc + ((size_t)b * NT3) * D_ + j;
        float s = 0.f;
        #pragma unroll 8
        for (int i = 0; i < NT3; i++) s = fmaf(base[(size_t)i * D_], s_scale[i], s);
        s_zh[j] = s * invL;
    }
    __syncthreads();

    for (int j = tid; j < D_; j += 256) {
        const float4* wr = (const float4*)(g_M + (size_t)j * D_);
        float s = 0.f;
        #pragma unroll 8
        for (int i = 0; i < D_ / 4; i++) {
            float4 w = wr[i];
            s += w.x * s_zh[4*i] + w.y * s_zh[4*i+1] + w.z * s_zh[4*i+2] + w.w * s_zh[4*i+3];
        }
        s_z[j] = s + g_d[j];
    }
    __syncthreads();

    for (int j = tid; j < D_; j += 256) {
        const float4* wr = (const float4*)(pw1 + (size_t)j * D_);
        float s = 0.f;
        #pragma unroll 8
        for (int i = 0; i < D_ / 4; i++) {
            float4 w = wr[i];
            s += w.x * s_z[4*i] + w.y * s_z[4*i+1] + w.z * s_z[4*i+2] + w.w * s_z[4*i+3];
        }
        s_h[j] = gelu_f(s + pb1[j]);
    }
    __syncthreads();

    for (int c = tid; c < NC; c += 256) {
        const float4* wr = (const float4*)(pw2 + (size_t)c * D_);
        float s = 0.f;
        #pragma unroll 8
        for (int i = 0; i < D_ / 4; i++) {
            float4 w = wr[i];
            s += w.x * s_h[4*i] + w.y * s_h[4*i+1] + w.z * s_h[4*i+2] + w.w * s_h[4*i+3];
        }
        out[(size_t)b * NC + c] = s + pb2[c];
    }
}

// =========================================================================
extern "C" void kernel_launch(void* const* d_in, const int* in_sizes, int n_in,
                              void* d_out, int out_size)
{
    const float* x_items = (const float*)d_in[0];
    const float* x_query = (const float*)d_in[1];
    const float* pxw1    = (const float*)d_in[2];
    const float* pxb1    = (const float*)d_in[3];
    const float* pxw2    = (const float*)d_in[4];
    const float* pxb2    = (const float*)d_in[5];
    const float* pqw1    = (const float*)d_in[6];
    const float* pqb1    = (const float*)d_in[7];
    const float* pqw2    = (const float*)d_in[8];
    const float* pqb2    = (const float*)d_in[9];
    const float* qw      = (const float*)d_in[10];
    const float* qb      = (const float*)d_in[11];
    const float* kw      = (const float*)d_in[12];
    const float* kb      = (const float*)d_in[13];
    const float* vw      = (const float*)d_in[14];
    const float* vb      = (const float*)d_in[15];
    const float* pw1     = (const float*)d_in[16];
    const float* pb1     = (const float*)d_in[17];
    const float* pw2     = (const float*)d_in[18];
    const float* pb2     = (const float*)d_in[19];
    float* out = (float*)d_out;

    cudaFuncSetAttribute(k_main, cudaFuncAttributeMaxDynamicSharedMemorySize, SMEM_MAIN);

    k_conv<<<256, 256>>>(pxw1);
    k_prep<<<128, 256>>>(kw, pxw2, pxb2, vw, vb);
    k_query<<<B_, D_>>>(x_query, pqw1, pqb1, pqw2, pqb2, qw, qb, kb);
    k_main<<<dim3(NT3, B_), 256, SMEM_MAIN>>>(x_items, pxb1);
    k_final<<<B_, 256>>>(pw1, pb1, pw2, pb2, out);
}

// round 17
// speedup vs baseline: 10.8747x; 1.2474x over previous
#include <cuda_runtime.h>
#include <cuda_bf16.h>
#include <cuda_fp16.h>
#include <math.h>
#include <stddef.h>
#include <stdint.h>

#define B_  32
#define N_  8192
#define DI  128
#define D_  512
#define NC  1000
#define TM  64            // items per tile
#define NT3 128           // tiles per batch

// ---------------- device scratch (static allocation only) ----------------
// NOTE: these are referenced ONLY from device code. Passing a __device__
// symbol as a host-side kernel argument passes the host shadow address and
// silently corrupts (root cause of the round-5..10 1.15e-3 bug).
__device__ float g_P[D_ * D_];           // kw @ w2   (score fold)
__device__ float g_e[D_];                // kw @ b2
__device__ float g_M[D_ * D_];           // vw @ w2   (value fold)
__device__ float g_d[D_];                // vw @ b2 + vb
__device__ float g_h1q[B_ * D_];         // query h1
__device__ float g_h2q[B_ * D_];         // query h2
__device__ float g_qv[B_ * D_];          // per-batch q vector
__device__ float g_u[B_ * D_];           // per-batch score vector (H1 space)
__device__ float g_c[B_];                // per-batch score constant
__device__ float g_pm[B_ * NT3];         // per-tile softmax max
__device__ float g_pl[B_ * NT3];         // per-tile softmax sum
__device__ float g_scale[B_ * NT3];      // per-tile rescale
__device__ float g_invL[B_];             // 1/L per batch
__device__ float g_zh[B_ * D_];          // combined weighted H1
__device__ float g_z[B_ * D_];           // value-projected z
__device__ float g_hh[B_ * D_];          // phi hidden
__device__ float g_pacc[B_ * NT3 * D_];  // per-tile weighted H1 accum (8.4 MB)
__device__ __align__(16) __half g_h1[(size_t)B_ * N_ * D_];  // H1 scratch
__device__ __align__(16) __half g_w1f[D_ * DI];              // W1 fp16

__device__ __forceinline__ float gelu_f(float x) {
    return 0.5f * x * (1.0f + erff(x * 0.70710678118654752440f));
}
__device__ __forceinline__ uint32_t smem_u32(const void* p) {
    uint32_t a;
    asm("{ .reg .u64 t; cvta.to.shared.u64 t, %1; cvt.u32.u64 %0, t; }" : "=r"(a) : "l"(p));
    return a;
}
__device__ __forceinline__ void ldsm4(uint32_t* r, uint32_t addr) {
    asm volatile("ldmatrix.sync.aligned.m8n8.x4.shared.b16 {%0,%1,%2,%3}, [%4];"
        : "=r"(r[0]), "=r"(r[1]), "=r"(r[2]), "=r"(r[3]) : "r"(addr));
}
__device__ __forceinline__ void mma_f16(float* c, const uint32_t* a, uint32_t b0, uint32_t b1) {
    asm volatile("mma.sync.aligned.m16n8k16.row.col.f32.f16.f16.f32 "
        "{%0,%1,%2,%3}, {%4,%5,%6,%7}, {%8,%9}, {%0,%1,%2,%3};"
        : "+f"(c[0]), "+f"(c[1]), "+f"(c[2]), "+f"(c[3])
        : "r"(a[0]), "r"(a[1]), "r"(a[2]), "r"(a[3]), "r"(b0), "r"(b1));
}
#define CP_ASYNC16(dst, src) asm volatile("cp.async.cg.shared.global [%0], [%1], 16;" :: "r"(dst), "l"(src) : "memory")
#define CP_COMMIT()          asm volatile("cp.async.commit_group;" ::: "memory")
#define CP_WAIT1()           asm volatile("cp.async.wait_group 1;" ::: "memory")
#define CP_WAIT0()           asm volatile("cp.async.wait_group 0;" ::: "memory")

// ---------------- k_main SMEM layout (bytes) ----------------
#define AS 272
#define A_HALF (TM * AS)              // 17408 (Xh or Xl)
#define OFF_A   0                      // hi, then lo -> 34816
#define W_CHUNK (64 * AS)              // 17408 (Wh only, one 64-dim chunk)
#define OFF_W  (2 * A_HALF)            // 34816; double buffer -> 69632
#define OFF_U  (OFF_W + 2 * W_CHUNK)   // 69632; 512 floats
#define OFF_B1 (OFF_U + 2048)          // 71680
#define OFF_SP (OFF_B1 + 2048)         // 73728
#define OFF_PR (OFF_SP + 512)          // 74240
#define SMEM_MAIN (OFF_PR + 256 + 64)  // 74560 -> 2 CTAs/SM

// =========================================================================
// k_conv: W1 -> fp16. grid=256, block=256
// =========================================================================
__global__ __launch_bounds__(256) void k_conv(const float* __restrict__ w1) {
    int i = blockIdx.x * 256 + threadIdx.x;
    g_w1f[i] = __float2half_rn(w1[i]);
}

// =========================================================================
// k_prep: folded weight products (trusted). grid=128, block=256
// =========================================================================
__global__ __launch_bounds__(256) void k_prep(
    const float* __restrict__ kw, const float* __restrict__ w2,
    const float* __restrict__ b2, const float* __restrict__ vw,
    const float* __restrict__ vb)
{
    __shared__ float sA[8][D_];
    const int blk = blockIdx.x;
    const bool isM = blk >= 64;
    const int r0 = (blk & 63) * 8;
    const float* A = isM ? vw : kw;
    const int tid = threadIdx.x;

    for (int e = tid; e < 8 * (D_ / 4); e += 256) {
        int r = e / (D_ / 4), c = e % (D_ / 4);
        ((float4*)sA[r])[c] = ((const float4*)(A + (size_t)(r0 + r) * D_))[c];
    }
    __syncthreads();

    float* OUT = isM ? g_M : g_P;
    for (int j = tid; j < D_; j += 256) {
        float acc[8] = {};
        #pragma unroll 4
        for (int k = 0; k < D_; k++) {
            float wv = w2[(size_t)k * D_ + j];
            #pragma unroll
            for (int r = 0; r < 8; r++) acc[r] = fmaf(sA[r][k], wv, acc[r]);
        }
        #pragma unroll
        for (int r = 0; r < 8; r++) OUT[(size_t)(r0 + r) * D_ + j] = acc[r];
    }
    if (tid < 8) {
        float s = 0.f;
        #pragma unroll 8
        for (int k = 0; k < D_; k++) s = fmaf(sA[tid][k], b2[k], s);
        if (isM) g_d[r0 + tid] = s + vb[r0 + tid];
        else     g_e[r0 + tid] = s;
    }
}

// =========================================================================
// Query path, parallel stages (device scratch referenced in-kernel only)
// =========================================================================
__global__ __launch_bounds__(512) void k_q1(
    const float* __restrict__ x_query,
    const float* __restrict__ w1, const float* __restrict__ b1)
{
    const int b = blockIdx.x, j = threadIdx.x;
    g_h1q[b * D_ + j] = gelu_f(fmaf(x_query[b], w1[j], b1[j]));
}

// h2 = w2q @ h1 + b2. grid=(8, B_), block=256
__global__ __launch_bounds__(256) void k_qh2(
    const float* __restrict__ w, const float* __restrict__ bias)
{
    __shared__ float sh[D_];
    const int b = blockIdx.y, j0 = blockIdx.x * 64, tid = threadIdx.x;
    for (int j = tid; j < D_; j += 256) sh[j] = g_h1q[b * D_ + j];
    __syncthreads();
    const int jj = j0 + (tid >> 2), part = tid & 3;
    const float4* wr = (const float4*)(w + (size_t)jj * D_ + part * 128);
    const float* hp = sh + part * 128;
    float s = 0.f;
    #pragma unroll 8
    for (int i = 0; i < 32; i++) {
        float4 wv = wr[i];
        s += wv.x * hp[4*i] + wv.y * hp[4*i+1] + wv.z * hp[4*i+2] + wv.w * hp[4*i+3];
    }
    s += __shfl_xor_sync(0xffffffffu, s, 1);
    s += __shfl_xor_sync(0xffffffffu, s, 2);
    if (part == 0) g_h2q[b * D_ + jj] = s + bias[jj];
}

// qv = qw @ h2 + qb. grid=(8, B_), block=256
__global__ __launch_bounds__(256) void k_qqv(
    const float* __restrict__ w, const float* __restrict__ bias)
{
    __shared__ float sh[D_];
    const int b = blockIdx.y, j0 = blockIdx.x * 64, tid = threadIdx.x;
    for (int j = tid; j < D_; j += 256) sh[j] = g_h2q[b * D_ + j];
    __syncthreads();
    const int jj = j0 + (tid >> 2), part = tid & 3;
    const float4* wr = (const float4*)(w + (size_t)jj * D_ + part * 128);
    const float* hp = sh + part * 128;
    float s = 0.f;
    #pragma unroll 8
    for (int i = 0; i < 32; i++) {
        float4 wv = wr[i];
        s += wv.x * hp[4*i] + wv.y * hp[4*i+1] + wv.z * hp[4*i+2] + wv.w * hp[4*i+3];
    }
    s += __shfl_xor_sync(0xffffffffu, s, 1);
    s += __shfl_xor_sync(0xffffffffu, s, 2);
    if (part == 0) g_qv[b * D_ + jj] = s + bias[jj];
}

// c = qv . (e + kb). grid=B_, block=512
__global__ __launch_bounds__(512) void k_qc(const float* __restrict__ kb) {
    __shared__ float red[16];
    const int b = blockIdx.x, j = threadIdx.x;
    float p = g_qv[b * D_ + j] * (g_e[j] + kb[j]);
    for (int o = 16; o; o >>= 1) p += __shfl_down_sync(0xffffffffu, p, o);
    if ((j & 31) == 0) red[j >> 5] = p;
    __syncthreads();
    if (j == 0) {
        float t = 0.f;
        for (int i = 0; i < 16; i++) t += red[i];
        g_c[b] = t;
    }
}

// u = P^T qv. grid=(8, B_), block=256
__global__ __launch_bounds__(256) void k_qu() {
    __shared__ float sq[D_];
    __shared__ float red[4][64];
    const int b = blockIdx.y, j0 = blockIdx.x * 64, tid = threadIdx.x;
    for (int j = tid; j < D_; j += 256) sq[j] = g_qv[b * D_ + j];
    __syncthreads();
    const int jl = tid & 63, mq = tid >> 6;
    float acc = 0.f;
    #pragma unroll 8
    for (int m = mq; m < D_; m += 4)
        acc = fmaf(sq[m], g_P[(size_t)m * D_ + j0 + jl], acc);
    red[mq][jl] = acc;
    __syncthreads();
    if (tid < 64)
        g_u[b * D_ + j0 + tid] = red[0][tid] + red[1][tid] + red[2][tid] + red[3][tid];
}

// =========================================================================
// k_main: fp16 2-term HMMA GEMM1 + gelu + scores + softmax partials.
// grid=(NT3, B_), block=256 (unchanged from round 16)
// =========================================================================
__device__ __forceinline__ void load_w_async(int c, uint32_t wbuf, int tid) {
    #pragma unroll
    for (int it = 0; it < 4; ++it) {
        int e = it * 256 + tid;
        int r = e >> 4, seg = e & 15;
        uint32_t dst = wbuf + r * AS + seg * 16;
        const __half* src = g_w1f + (size_t)(c * 64 + r) * DI + seg * 8;
        CP_ASYNC16(dst, src);
    }
}

__global__ __launch_bounds__(256, 2) void k_main(
    const float* __restrict__ x_items,
    const float* __restrict__ b1)
{
    extern __shared__ char sm[];
    const uint32_t sb = smem_u32(sm);
    const int tile = blockIdx.x;
    const int b    = blockIdx.y;
    const int tid  = threadIdx.x;
    const int wid  = tid >> 5;
    const int lane = tid & 31;
    const int mw   = wid & 3;
    const int nh   = wid >> 2;
    const int n0   = tile * TM;
    const int q    = lane >> 2, t4 = lane & 3;

    float* su  = (float*)(sm + OFF_U);
    float* sb1 = (float*)(sm + OFF_B1);
    float* sp  = (float*)(sm + OFF_SP);
    float* spr = (float*)(sm + OFF_PR);

    __half2* h1g = (__half2*)(g_h1 + ((size_t)(b * NT3 + tile) * TM) * D_);

    for (int j = tid; j < D_; j += 256) { su[j] = g_u[b * D_ + j]; sb1[j] = b1[j]; }

    {
        const float4* xs = (const float4*)(x_items + ((size_t)b * N_ + n0) * DI);
        #pragma unroll
        for (int it = 0; it < 8; ++it) {
            int e = it * 256 + tid;
            int i = e >> 5, qd = e & 31;
            float4 v = xs[i * 32 + qd];
            __half h0 = __float2half_rn(v.x), h1v = __float2half_rn(v.y);
            __half h2v = __float2half_rn(v.z), h3 = __float2half_rn(v.w);
            __half l0 = __float2half_rn(v.x - __half2float(h0));
            __half l1 = __float2half_rn(v.y - __half2float(h1v));
            __half l2 = __float2half_rn(v.z - __half2float(h2v));
            __half l3 = __float2half_rn(v.w - __half2float(h3));
            __half2 hp0 = __halves2half2(h0, h1v), hp1 = __halves2half2(h2v, h3);
            __half2 lp0 = __halves2half2(l0, l1),  lp1 = __halves2half2(l2, l3);
            int off = i * AS + qd * 8;
            *(uint32_t*)(sm + OFF_A + off)              = *(uint32_t*)&hp0;
            *(uint32_t*)(sm + OFF_A + off + 4)          = *(uint32_t*)&hp1;
            *(uint32_t*)(sm + OFF_A + A_HALF + off)     = *(uint32_t*)&lp0;
            *(uint32_t*)(sm + OFF_A + A_HALF + off + 4) = *(uint32_t*)&lp1;
        }
    }
    load_w_async(0, sb + OFF_W, tid);
    CP_COMMIT();

    const uint32_t arow_hi = sb + OFF_A + (mw * 16 + (lane & 15)) * AS + (lane >> 4) * 16;
    const uint32_t arow_lo = arow_hi + A_HALF;
    const uint32_t brow_off = (nh * 32 + (lane & 7) + ((lane >> 4) & 1) * 8) * AS + ((lane >> 3) & 1) * 16;

    float s0 = 0.f, s1 = 0.f;

    for (int c = 0; c < 8; ++c) {
        const int buf = c & 1;
        if (c < 7) {
            load_w_async(c + 1, sb + OFF_W + (buf ^ 1) * W_CHUNK, tid);
            CP_COMMIT();
            CP_WAIT1();
        } else {
            CP_WAIT0();
        }
        __syncthreads();

        float acc[4][4] = {};
        const uint32_t brow_hi = sb + OFF_W + buf * W_CHUNK + brow_off;
        #pragma unroll
        for (int ks = 0; ks < 8; ++ks) {
            uint32_t ah[4], al[4];
            ldsm4(ah, arow_hi + ks * 32);
            ldsm4(al, arow_lo + ks * 32);
            #pragma unroll
            for (int p = 0; p < 2; ++p) {
                uint32_t bh[4];
                ldsm4(bh, brow_hi + p * 16 * AS + ks * 32);
                mma_f16(acc[2*p],   ah, bh[0], bh[1]);
                mma_f16(acc[2*p+1], ah, bh[2], bh[3]);
                mma_f16(acc[2*p],   al, bh[0], bh[1]);
                mma_f16(acc[2*p+1], al, bh[2], bh[3]);
            }
        }
        __syncthreads();

        const int jb = c * 64 + nh * 32;
        const int r0 = mw * 16 + q;
        #pragma unroll
        for (int nt = 0; nt < 4; ++nt) {
            int j0 = jb + nt * 8 + t4 * 2;
            float b0v = sb1[j0], b1v = sb1[j0 + 1];
            float u0 = su[j0], u1 = su[j0 + 1];
            float h00 = gelu_f(acc[nt][0] + b0v);
            float h01 = gelu_f(acc[nt][1] + b1v);
            float h10 = gelu_f(acc[nt][2] + b0v);
            float h11 = gelu_f(acc[nt][3] + b1v);
            s0 = fmaf(h00, u0, fmaf(h01, u1, s0));
            s1 = fmaf(h10, u0, fmaf(h11, u1, s1));
            h1g[r0 * 256 + (j0 >> 1)]       = __floats2half2_rn(h00, h01);
            h1g[(r0 + 8) * 256 + (j0 >> 1)] = __floats2half2_rn(h10, h11);
        }
    }

    s0 += __shfl_xor_sync(0xffffffffu, s0, 1);
    s0 += __shfl_xor_sync(0xffffffffu, s0, 2);
    s1 += __shfl_xor_sync(0xffffffffu, s1, 1);
    s1 += __shfl_xor_sync(0xffffffffu, s1, 2);
    if (t4 == 0) {
        sp[nh * 64 + mw * 16 + q]     = s0;
        sp[nh * 64 + mw * 16 + q + 8] = s1;
    }
    __syncthreads();

    if (wid == 0) {
        const float cb = g_c[b];
        float v0 = (sp[lane] + sp[64 + lane] + cb) * 0.044194173824159216f;
        float v1 = (sp[32 + lane] + sp[96 + lane] + cb) * 0.044194173824159216f;
        float m = fmaxf(v0, v1);
        for (int o = 16; o; o >>= 1) m = fmaxf(m, __shfl_xor_sync(0xffffffffu, m, o));
        float p0 = expf(v0 - m), p1 = expf(v1 - m);
        float l = p0 + p1;
        for (int o = 16; o; o >>= 1) l += __shfl_xor_sync(0xffffffffu, l, o);
        spr[lane] = p0;
        spr[lane + 32] = p1;
        if (lane == 0) {
            g_pm[b * NT3 + tile] = m;
            g_pl[b * NT3 + tile] = l;
        }
    }
    __syncthreads();

    {
        float ax = 0.f, ay = 0.f;
        const __half2* h1c = h1g + tid;
        #pragma unroll 8
        for (int i = 0; i < TM; ++i) {
            float2 h = __half22float2(h1c[i * 256]);
            float p = spr[i];
            ax = fmaf(p, h.x, ax);
            ay = fmaf(p, h.y, ay);
        }
        float2* dst = (float2*)(g_pacc + ((size_t)(b * NT3 + tile)) * D_) + tid;
        *dst = make_float2(ax, ay);
    }
}

// =========================================================================
// Final path, parallel stages
// =========================================================================
// k_scale: per-batch global max/denominator. grid=B_, block=NT3
__global__ __launch_bounds__(NT3) void k_scale() {
    __shared__ float red[4];
    const int b = blockIdx.x, t = threadIdx.x;
    const int lane = t & 31, w = t >> 5;
    float pm = g_pm[b * NT3 + t];
    float m = pm;
    for (int o = 16; o; o >>= 1) m = fmaxf(m, __shfl_xor_sync(0xffffffffu, m, o));
    if (lane == 0) red[w] = m;
    __syncthreads();
    float M = fmaxf(fmaxf(red[0], red[1]), fmaxf(red[2], red[3]));
    float sc = expf(pm - M);
    g_scale[b * NT3 + t] = sc;
    float l = g_pl[b * NT3 + t] * sc;
    for (int o = 16; o; o >>= 1) l += __shfl_xor_sync(0xffffffffu, l, o);
    __syncthreads();
    if (lane == 0) red[w] = l;
    __syncthreads();
    if (t == 0) g_invL[b] = 1.0f / (red[0] + red[1] + red[2] + red[3]);
}

// k_zh: zh[b][j] = invL * sum_t scale[t] * pacc[t][j]. grid=(4, B_), block=128
__global__ __launch_bounds__(128) void k_zh() {
    __shared__ float ssc[NT3];
    const int b = blockIdx.y;
    const int j = blockIdx.x * 128 + threadIdx.x;
    ssc[threadIdx.x] = g_scale[b * NT3 + threadIdx.x];
    __syncthreads();
    const float* base = g_pacc + ((size_t)b * NT3) * D_ + j;
    float s = 0.f;
    #pragma unroll 8
    for (int t = 0; t < NT3; ++t) s = fmaf(base[(size_t)t * D_], ssc[t], s);
    g_zh[b * D_ + j] = s * g_invL[b];
}

// k_fz: z = M_fold @ zh + d. grid=(8, B_), block=256
__global__ __launch_bounds__(256) void k_fz() {
    __shared__ float sh[D_];
    const int b = blockIdx.y, j0 = blockIdx.x * 64, tid = threadIdx.x;
    for (int j = tid; j < D_; j += 256) sh[j] = g_zh[b * D_ + j];
    __syncthreads();
    const int jj = j0 + (tid >> 2), part = tid & 3;
    const float4* wr = (const float4*)(g_M + (size_t)jj * D_ + part * 128);
    const float* hp = sh + part * 128;
    float s = 0.f;
    #pragma unroll 8
    for (int i = 0; i < 32; i++) {
        float4 wv = wr[i];
        s += wv.x * hp[4*i] + wv.y * hp[4*i+1] + wv.z * hp[4*i+2] + wv.w * hp[4*i+3];
    }
    s += __shfl_xor_sync(0xffffffffu, s, 1);
    s += __shfl_xor_sync(0xffffffffu, s, 2);
    if (part == 0) g_z[b * D_ + jj] = s + g_d[jj];
}

// k_fh: h = gelu(pw1 @ z + pb1). grid=(8, B_), block=256
__global__ __launch_bounds__(256) void k_fh(
    const float* __restrict__ pw1, const float* __restrict__ pb1)
{
    __shared__ float sh[D_];
    const int b = blockIdx.y, j0 = blockIdx.x * 64, tid = threadIdx.x;
    for (int j = tid; j < D_; j += 256) sh[j] = g_z[b * D_ + j];
    __syncthreads();
    const int jj = j0 + (tid >> 2), part = tid & 3;
    const float4* wr = (const float4*)(pw1 + (size_t)jj * D_ + part * 128);
    const float* hp = sh + part * 128;
    float s = 0.f;
    #pragma unroll 8
    for (int i = 0; i < 32; i++) {
        float4 wv = wr[i];
        s += wv.x * hp[4*i] + wv.y * hp[4*i+1] + wv.z * hp[4*i+2] + wv.w * hp[4*i+3];
    }
    s += __shfl_xor_sync(0xffffffffu, s, 1);
    s += __shfl_xor_sync(0xffffffffu, s, 2);
    if (part == 0) g_hh[b * D_ + jj] = gelu_f(s + pb1[jj]);
}

// k_fo: out = pw2 @ h + pb2. grid=(16, B_), block=256
__global__ __launch_bounds__(256) void k_fo(
    const float* __restrict__ pw2, const float* __restrict__ pb2,
    float* __restrict__ out)
{
    __shared__ float sh[D_];
    const int b = blockIdx.y, j0 = blockIdx.x * 64, tid = threadIdx.x;
    for (int j = tid; j < D_; j += 256) sh[j] = g_hh[b * D_ + j];
    __syncthreads();
    const int jj = j0 + (tid >> 2), part = tid & 3;
    const int jr = jj < NC ? jj : NC - 1;   // clamp OOB rows (guarded store)
    const float4* wr = (const float4*)(pw2 + (size_t)jr * D_ + part * 128);
    const float* hp = sh + part * 128;
    float s = 0.f;
    #pragma unroll 8
    for (int i = 0; i < 32; i++) {
        float4 wv = wr[i];
        s += wv.x * hp[4*i] + wv.y * hp[4*i+1] + wv.z * hp[4*i+2] + wv.w * hp[4*i+3];
    }
    s += __shfl_xor_sync(0xffffffffu, s, 1);
    s += __shfl_xor_sync(0xffffffffu, s, 2);
    if (part == 0 && jj < NC) out[(size_t)b * NC + jj] = s + pb2[jj];
}

// =========================================================================
extern "C" void kernel_launch(void* const* d_in, const int* in_sizes, int n_in,
                              void* d_out, int out_size)
{
    const float* x_items = (const float*)d_in[0];
    const float* x_query = (const float*)d_in[1];
    const float* pxw1    = (const float*)d_in[2];
    const float* pxb1    = (const float*)d_in[3];
    const float* pxw2    = (const float*)d_in[4];
    const float* pxb2    = (const float*)d_in[5];
    const float* pqw1    = (const float*)d_in[6];
    const float* pqb1    = (const float*)d_in[7];
    const float* pqw2    = (const float*)d_in[8];
    const float* pqb2    = (const float*)d_in[9];
    const float* qw      = (const float*)d_in[10];
    const float* qb      = (const float*)d_in[11];
    const float* kw      = (const float*)d_in[12];
    const float* kb      = (const float*)d_in[13];
    const float* vw      = (const float*)d_in[14];
    const float* vb      = (const float*)d_in[15];
    const float* pw1     = (const float*)d_in[16];
    const float* pb1     = (const float*)d_in[17];
    const float* pw2     = (const float*)d_in[18];
    const float* pb2     = (const float*)d_in[19];
    float* out = (float*)d_out;

    cudaFuncSetAttribute(k_main, cudaFuncAttributeMaxDynamicSharedMemorySize, SMEM_MAIN);

    k_conv<<<256, 256>>>(pxw1);
    k_prep<<<128, 256>>>(kw, pxw2, pxb2, vw, vb);
    k_q1<<<B_, D_>>>(x_query, pqw1, pqb1);
    k_qh2<<<dim3(8, B_), 256>>>(pqw2, pqb2);
    k_qqv<<<dim3(8, B_), 256>>>(qw, qb);
    k_qc<<<B_, D_>>>(kb);
    k_qu<<<dim3(8, B_), 256>>>();
    k_main<<<dim3(NT3, B_), 256, SMEM_MAIN>>>(x_items, pxb1);
    k_scale<<<B_, NT3>>>();
    k_zh<<<dim3(4, B_), 128>>>();
    k_fz<<<dim3(8, B_), 256>>>();
    k_fh<<<dim3(8, B_), 256>>>(pw1, pb1);
    k_fo<<<dim3(16, B_), 256>>>(pw2, pb2, out);
}